// round 2
// baseline (speedup 1.0000x reference)
#include <cuda_runtime.h>
#include <math.h>

// ---------------- problem constants ----------------
#define BB   2
#define SS   4096
#define DDIM 768
#define FF   3072
#define NHH  12
#define DH   64
#define WW   128
#define NGG  32
#define CC   (SS/WW)      // 32 chunks
#define MM   (BB*SS)      // 8192 rows

// ---------------- scratch (static device arrays; no allocs allowed) ----------
__device__ float g_q   [BB*NHH*SS*DH];
__device__ float g_k   [BB*NHH*SS*DH];
__device__ float g_v   [BB*NHH*SS*DH];
__device__ float g_ctx [BB*SS*DDIM];
__device__ float g_x1  [BB*SS*DDIM];
__device__ float g_attn[BB*SS*DDIM];
__device__ float g_int [BB*SS*FF];
__device__ float g_x2  [BB*SS*DDIM];

// ---------------- GEMM: C[M,N] = A[M,K] @ B[K,N] + bias, fused epilogues ----
#define GBM 128
#define GBN 128
#define GBK 8

#define EP_PLAIN 0
#define EP_QKV   1   // write permuted [b][h][s][d], scaled
#define EP_RES   2   // += residual R[m*N+n]
#define EP_GELU  3   // exact gelu

__global__ __launch_bounds__(256)
void sgemm_ep(const float* __restrict__ A, const float* __restrict__ B,
              const float* __restrict__ bias, const float* __restrict__ R,
              float* __restrict__ C, int M, int N, int K, int mode, float scale)
{
    __shared__ float As[GBK][GBM];
    __shared__ float Bs[GBK][GBN];
    const int tid = threadIdx.x;
    const int tx = tid & 15, ty = tid >> 4;
    const int bm = blockIdx.y * GBM, bn = blockIdx.x * GBN;

    float acc[8][8];
#pragma unroll
    for (int i = 0; i < 8; i++)
#pragma unroll
        for (int j = 0; j < 8; j++) acc[i][j] = 0.f;

    const int arow = tid >> 1;          // 0..127
    const int acol = (tid & 1) * 4;     // 0 or 4
    const int brow = tid >> 5;          // 0..7
    const int bcol = (tid & 31) * 4;    // 0..124

    for (int k0 = 0; k0 < K; k0 += GBK) {
        float4 av = *(const float4*)&A[(size_t)(bm + arow) * K + k0 + acol];
        As[acol + 0][arow] = av.x;
        As[acol + 1][arow] = av.y;
        As[acol + 2][arow] = av.z;
        As[acol + 3][arow] = av.w;
        float4 bv = *(const float4*)&B[(size_t)(k0 + brow) * N + bn + bcol];
        *(float4*)&Bs[brow][bcol] = bv;
        __syncthreads();
#pragma unroll
        for (int kk = 0; kk < GBK; kk++) {
            float a[8], b[8];
            *(float4*)&a[0] = *(const float4*)&As[kk][ty * 8];
            *(float4*)&a[4] = *(const float4*)&As[kk][ty * 8 + 4];
            *(float4*)&b[0] = *(const float4*)&Bs[kk][tx * 8];
            *(float4*)&b[4] = *(const float4*)&Bs[kk][tx * 8 + 4];
#pragma unroll
            for (int i = 0; i < 8; i++)
#pragma unroll
                for (int j = 0; j < 8; j++)
                    acc[i][j] += a[i] * b[j];
        }
        __syncthreads();
    }

#pragma unroll
    for (int i = 0; i < 8; i++) {
        const int m = bm + ty * 8 + i;
        const int bidx = m / SS, s = m % SS;  // only used in QKV mode
#pragma unroll
        for (int j = 0; j < 8; j++) {
            const int n = bn + tx * 8 + j;
            float val = acc[i][j] + bias[n];
            if (mode == EP_QKV) {
                val *= scale;
                const int h = n >> 6, d = n & 63;
                C[(((size_t)(bidx * NHH + h)) * SS + s) * DH + d] = val;
            } else if (mode == EP_RES) {
                C[(size_t)m * N + n] = val + R[(size_t)m * N + n];
            } else if (mode == EP_GELU) {
                C[(size_t)m * N + n] = 0.5f * val * (1.f + erff(val * 0.70710678118654752f));
            } else {
                C[(size_t)m * N + n] = val;
            }
        }
    }
}

// ---------------- local (banded) attention: one block = (chunk c, bh) -------
// smem: k band 384x64, v band 384x64, global k 32x64, global v 32x64, am 416
#define LOC_SMEM ((384*64*2 + 32*64*2 + 384 + 32) * sizeof(float))

__global__ __launch_bounds__(128)
void local_attn(const float* __restrict__ q, const float* __restrict__ k,
                const float* __restrict__ v, const float* __restrict__ am,
                float* __restrict__ ctx)
{
    extern __shared__ float sm[];
    float* ks  = sm;                  // [384][64]
    float* vs  = ks + 384 * 64;       // [384][64]
    float* gks = vs + 384 * 64;       // [32][64]
    float* gvs = gks + 32 * 64;       // [32][64]
    float* ams = gvs + 32 * 64;       // [384 band + 32 global]

    const int c = blockIdx.x, bh = blockIdx.y;
    const int b = bh / NHH, h = bh % NHH;
    const int tid = threadIdx.x;
    const float* kb = k + (size_t)bh * SS * DH;
    const float* vb = v + (size_t)bh * SS * DH;
    const int base = c * WW - WW;      // key position of band slot 0

    for (int i = tid; i < 384 * 64; i += 128) {
        const int j = i >> 6, d = i & 63;
        const int kp = base + j;
        const bool in = (kp >= 0 && kp < SS);
        ks[i] = in ? kb[(size_t)kp * DH + d] : 0.f;
        vs[i] = in ? vb[(size_t)kp * DH + d] : 0.f;
    }
    for (int i = tid; i < 32 * 64; i += 128) {
        gks[i] = kb[i];
        gvs[i] = vb[i];
    }
    for (int j = tid; j < 384; j += 128) {
        const int kp = base + j;
        ams[j] = (kp >= 0 && kp < SS) ? am[b * SS + kp] : 0.f;
    }
    if (tid < 32) ams[384 + tid] = am[b * SS + tid];
    __syncthreads();

    const int s = c * WW + tid;       // this thread's query position
    float qr[64];
    const float* qp = q + ((size_t)bh * SS + s) * DH;
#pragma unroll
    for (int d = 0; d < 64; d += 4) {
        float4 t = *(const float4*)&qp[d];
        qr[d] = t.x; qr[d + 1] = t.y; qr[d + 2] = t.z; qr[d + 3] = t.w;
    }

    float mval = -1e30f, l = 0.f;
    float acc[64];
#pragma unroll
    for (int d = 0; d < 64; d++) acc[d] = 0.f;

    // band keys (skip masked slots — exp(NEG - max) == 0 exactly in fp32)
    for (int j = 0; j < 384; j++) {
        const int kp = base + j;
        const int dlt = kp - s;
        if (dlt < -WW || dlt > WW || kp < NGG || kp >= SS) continue;
        const float* kr = &ks[j * 64];
        float s0 = 0.f, s1 = 0.f, s2 = 0.f, s3 = 0.f;
#pragma unroll
        for (int d = 0; d < 64; d += 4) {
            s0 += qr[d]     * kr[d];
            s1 += qr[d + 1] * kr[d + 1];
            s2 += qr[d + 2] * kr[d + 2];
            s3 += qr[d + 3] * kr[d + 3];
        }
        const float sc = (s0 + s1) + (s2 + s3) + ams[j];
        const float mn = fmaxf(mval, sc);
        const float corr = __expf(mval - mn);
        const float p = __expf(sc - mn);
        l = l * corr + p;
        const float* vr = &vs[j * 64];
#pragma unroll
        for (int d = 0; d < 64; d++) acc[d] = acc[d] * corr + p * vr[d];
        mval = mn;
    }
    // global keys (always valid)
    for (int j = 0; j < 32; j++) {
        const float* kr = &gks[j * 64];
        float s0 = 0.f, s1 = 0.f, s2 = 0.f, s3 = 0.f;
#pragma unroll
        for (int d = 0; d < 64; d += 4) {
            s0 += qr[d]     * kr[d];
            s1 += qr[d + 1] * kr[d + 1];
            s2 += qr[d + 2] * kr[d + 2];
            s3 += qr[d + 3] * kr[d + 3];
        }
        const float sc = (s0 + s1) + (s2 + s3) + ams[384 + j];
        const float mn = fmaxf(mval, sc);
        const float corr = __expf(mval - mn);
        const float p = __expf(sc - mn);
        l = l * corr + p;
        const float* vr = &gvs[j * 64];
#pragma unroll
        for (int d = 0; d < 64; d++) acc[d] = acc[d] * corr + p * vr[d];
        mval = mn;
    }

    if (s >= NGG) {
        const float inv = 1.f / l;
        float* op = ctx + ((size_t)(b * SS + s)) * DDIM + h * DH;
#pragma unroll
        for (int d = 0; d < 64; d++) op[d] = acc[d] * inv;
    }
}

// ---------------- global-row attention: one block = (global row g, bh) ------
__global__ __launch_bounds__(128)
void global_attn(const float* __restrict__ q, const float* __restrict__ k,
                 const float* __restrict__ v, const float* __restrict__ am,
                 float* __restrict__ ctx)
{
    __shared__ float lg[SS];      // 16 KB logits
    __shared__ float qs[64];
    __shared__ float red[128];

    const int g = blockIdx.x, bh = blockIdx.y;
    const int b = bh / NHH, h = bh % NHH;
    const int tid = threadIdx.x;

    if (tid < 64) qs[tid] = q[((size_t)bh * SS + g) * DH + tid];
    __syncthreads();

    const float* kb = k + (size_t)bh * SS * DH;
    for (int s = tid; s < SS; s += 128) {
        const float4* kr = (const float4*)&kb[(size_t)s * DH];
        float s0 = 0.f, s1 = 0.f, s2 = 0.f, s3 = 0.f;
#pragma unroll
        for (int d4 = 0; d4 < 16; d4++) {
            const float4 kv = kr[d4];
            s0 += qs[d4 * 4 + 0] * kv.x;
            s1 += qs[d4 * 4 + 1] * kv.y;
            s2 += qs[d4 * 4 + 2] * kv.z;
            s3 += qs[d4 * 4 + 3] * kv.w;
        }
        lg[s] = (s0 + s1) + (s2 + s3) + am[b * SS + s];
    }
    __syncthreads();

    // max reduction
    float mx = -1e30f;
    for (int s = tid; s < SS; s += 128) mx = fmaxf(mx, lg[s]);
    red[tid] = mx;
    __syncthreads();
    for (int st = 64; st > 0; st >>= 1) {
        if (tid < st) red[tid] = fmaxf(red[tid], red[tid + st]);
        __syncthreads();
    }
    mx = red[0];
    __syncthreads();

    // exp + sum reduction
    float sum = 0.f;
    for (int s = tid; s < SS; s += 128) {
        const float e = __expf(lg[s] - mx);
        lg[s] = e;
        sum += e;
    }
    red[tid] = sum;
    __syncthreads();
    for (int st = 64; st > 0; st >>= 1) {
        if (tid < st) red[tid] += red[tid + st];
        __syncthreads();
    }
    const float inv = 1.f / red[0];
    __syncthreads();

    // out[d] = sum_s p[s] * v[s][d]; 2 halves of keys across tid/64
    const float* vb = v + (size_t)bh * SS * DH;
    const int d = tid & 63, half = tid >> 6;
    float acc = 0.f;
    const int s0 = half * (SS / 2), s1 = s0 + SS / 2;
    for (int s = s0; s < s1; s++)
        acc += lg[s] * vb[(size_t)s * DH + d];
    red[tid] = acc;
    __syncthreads();
    if (tid < 64)
        ctx[((size_t)(b * SS + g)) * DDIM + h * DH + d] = (red[tid] + red[tid + 64]) * inv;
}

// ---------------- layernorm over last dim (768), eps 1e-12 ------------------
__global__ __launch_bounds__(256)
void layernorm_k(const float* __restrict__ X, const float* __restrict__ gw,
                 const float* __restrict__ bw, float* __restrict__ Y)
{
    __shared__ float xs[DDIM];
    __shared__ float red[256];
    const int row = blockIdx.x, tid = threadIdx.x;
    const float* xp = X + (size_t)row * DDIM;

    float sum = 0.f;
    for (int i = tid; i < DDIM; i += 256) { const float t = xp[i]; xs[i] = t; sum += t; }
    red[tid] = sum;
    __syncthreads();
    for (int st = 128; st > 0; st >>= 1) {
        if (tid < st) red[tid] += red[tid + st];
        __syncthreads();
    }
    const float mu = red[0] * (1.f / DDIM);
    __syncthreads();

    float vsum = 0.f;
    for (int i = tid; i < DDIM; i += 256) { const float d = xs[i] - mu; vsum += d * d; }
    red[tid] = vsum;
    __syncthreads();
    for (int st = 128; st > 0; st >>= 1) {
        if (tid < st) red[tid] += red[tid + st];
        __syncthreads();
    }
    const float rstd = rsqrtf(red[0] * (1.f / DDIM) + 1e-12f);
    for (int i = tid; i < DDIM; i += 256)
        Y[(size_t)row * DDIM + i] = (xs[i] - mu) * rstd * gw[i] + bw[i];
}

// ---------------- launch ----------------------------------------------------
extern "C" void kernel_launch(void* const* d_in, const int* in_sizes, int n_in,
                              void* d_out, int out_size)
{
    const float* h    = (const float*)d_in[0];
    const float* am   = (const float*)d_in[1];
    const float* Wq   = (const float*)d_in[2];
    const float* bq   = (const float*)d_in[3];
    const float* Wk   = (const float*)d_in[4];
    const float* bk   = (const float*)d_in[5];
    const float* Wv   = (const float*)d_in[6];
    const float* bv   = (const float*)d_in[7];
    const float* Wo   = (const float*)d_in[8];
    const float* bo   = (const float*)d_in[9];
    const float* ln1g = (const float*)d_in[10];
    const float* ln1b = (const float*)d_in[11];
    const float* Wi   = (const float*)d_in[12];
    const float* bi   = (const float*)d_in[13];
    const float* Wo2  = (const float*)d_in[14];
    const float* bo2  = (const float*)d_in[15];
    const float* ln2g = (const float*)d_in[16];
    const float* ln2b = (const float*)d_in[17];

    float *q, *k, *v, *ctx, *x1, *attn, *inter, *x2;
    cudaGetSymbolAddress((void**)&q,    g_q);
    cudaGetSymbolAddress((void**)&k,    g_k);
    cudaGetSymbolAddress((void**)&v,    g_v);
    cudaGetSymbolAddress((void**)&ctx,  g_ctx);
    cudaGetSymbolAddress((void**)&x1,   g_x1);
    cudaGetSymbolAddress((void**)&attn, g_attn);
    cudaGetSymbolAddress((void**)&inter,g_int);
    cudaGetSymbolAddress((void**)&x2,   g_x2);

    cudaFuncSetAttribute(local_attn, cudaFuncAttributeMaxDynamicSharedMemorySize,
                         (int)LOC_SMEM);

    const dim3 gD(DDIM / GBN, MM / GBM);     // (6, 64)
    const dim3 gF(FF / GBN,   MM / GBM);     // (24, 64)

    // QKV projections (permuted writes into [b][h][s][d]; q scaled by 1/8)
    sgemm_ep<<<gD, 256>>>(h, Wq, bq, nullptr, q, MM, DDIM, DDIM, EP_QKV, 0.125f);
    sgemm_ep<<<gD, 256>>>(h, Wk, bk, nullptr, k, MM, DDIM, DDIM, EP_QKV, 1.f);
    sgemm_ep<<<gD, 256>>>(h, Wv, bv, nullptr, v, MM, DDIM, DDIM, EP_QKV, 1.f);

    // attention
    local_attn<<<dim3(CC, BB * NHH), 128, LOC_SMEM>>>(q, k, v, am, ctx);
    global_attn<<<dim3(NGG, BB * NHH), 128>>>(q, k, v, am, ctx);

    // output projection + residual, LN1
    sgemm_ep<<<gD, 256>>>(ctx, Wo, bo, h, x1, MM, DDIM, DDIM, EP_RES, 1.f);
    layernorm_k<<<MM, 256>>>(x1, ln1g, ln1b, attn);

    // FFN
    sgemm_ep<<<gF, 256>>>(attn, Wi, bi, nullptr, inter, MM, FF, DDIM, EP_GELU, 1.f);
    sgemm_ep<<<gD, 256>>>(inter, Wo2, bo2, attn, x2, MM, DDIM, FF, EP_RES, 1.f);
    layernorm_k<<<MM, 256>>>(x2, ln2g, ln2b, (float*)d_out);
}

// round 7
// speedup vs baseline: 1.2194x; 1.2194x over previous
#include <cuda_runtime.h>
#include <cuda_bf16.h>
#include <math.h>
#include <stdint.h>

// ---------------- problem constants ----------------
#define BB   2
#define SS   4096
#define DDIM 768
#define FF   3072
#define NHH  12
#define DH   64
#define WW   128
#define NGG  32
#define CC   (SS/WW)      // 32 chunks
#define MM   (BB*SS)      // 8192 rows

typedef __nv_bfloat16 bf16;

// ---------------- scratch (static device arrays; no allocs allowed) ----------
__device__ float g_q   [BB*NHH*SS*DH];
__device__ float g_k   [BB*NHH*SS*DH];
__device__ float g_v   [BB*NHH*SS*DH];
__device__ float g_x1  [MM*DDIM];
__device__ float g_attn[MM*DDIM];
__device__ float g_x2  [MM*DDIM];

__device__ bf16 g_h_hi [MM*DDIM];
__device__ bf16 g_h_lo [MM*DDIM];
__device__ bf16 g_ctx_hi[MM*DDIM];
__device__ bf16 g_ctx_lo[MM*DDIM];
__device__ bf16 g_at_hi[MM*DDIM];
__device__ bf16 g_at_lo[MM*DDIM];
__device__ bf16 g_in_hi[(size_t)MM*FF];
__device__ bf16 g_in_lo[(size_t)MM*FF];

__device__ bf16 g_wqt_hi[DDIM*DDIM], g_wqt_lo[DDIM*DDIM];
__device__ bf16 g_wkt_hi[DDIM*DDIM], g_wkt_lo[DDIM*DDIM];
__device__ bf16 g_wvt_hi[DDIM*DDIM], g_wvt_lo[DDIM*DDIM];
__device__ bf16 g_wot_hi[DDIM*DDIM], g_wot_lo[DDIM*DDIM];
__device__ bf16 g_wit_hi[DDIM*FF],   g_wit_lo[DDIM*FF];    // [3072][768]
__device__ bf16 g_wo2t_hi[DDIM*FF],  g_wo2t_lo[DDIM*FF];   // [768][3072]

// ================= helpers =================
__device__ __forceinline__ uint32_t smem_u32(const void* p) {
    uint32_t a;
    asm("{ .reg .u64 t; cvta.to.shared.u64 t, %1; cvt.u32.u64 %0, t; }" : "=r"(a) : "l"(p));
    return a;
}
__device__ __forceinline__ void cpa16(uint32_t s, const void* g) {
    asm volatile("cp.async.cg.shared.global [%0], [%1], 16;\n" :: "r"(s), "l"(g));
}
__device__ __forceinline__ void ldsm4(uint32_t& r0, uint32_t& r1, uint32_t& r2, uint32_t& r3,
                                      uint32_t addr) {
    asm volatile("ldmatrix.sync.aligned.m8n8.x4.shared.b16 {%0,%1,%2,%3}, [%4];"
                 : "=r"(r0), "=r"(r1), "=r"(r2), "=r"(r3) : "r"(addr));
}
__device__ __forceinline__ void mma_bf16(float* c, const uint32_t* a, const uint32_t* b) {
    asm volatile("mma.sync.aligned.m16n8k16.row.col.f32.bf16.bf16.f32 "
                 "{%0,%1,%2,%3}, {%4,%5,%6,%7}, {%8,%9}, {%0,%1,%2,%3};"
                 : "+f"(c[0]), "+f"(c[1]), "+f"(c[2]), "+f"(c[3])
                 : "r"(a[0]), "r"(a[1]), "r"(a[2]), "r"(a[3]), "r"(b[0]), "r"(b[1]));
}

// ================= bf16 split GEMM: C[M,N] = (Ahi+Alo)(Bhi+Blo)^T ===========
// A: [M,K] bf16 hi/lo. B: [N,K] bf16 hi/lo (pre-transposed weights).
// Tile 128x128, K-chunk 64, 2-stage cp.async pipeline, SW128 smem, mma.sync.
#define GB_M 128
#define GB_N 128
#define GB_K 64
#define TILE_B 16384           // 128 rows x 128 bytes
#define STG_B  (4*TILE_B)      // Ahi,Alo,Bhi,Blo
#define GEMM_SMEM (2*STG_B)    // 128 KB

#define EP_QKV     0   // write permuted [b][h][s][d] fp32, (val+bias)*scale
#define EP_RES     1   // fp32 = val + bias + R
#define EP_GELU_BF 2   // bf16 hi/lo of gelu(val+bias)

__device__ __forceinline__ void gemm_load_stage(
    int tid, uint32_t sdata, int buf,
    const bf16* __restrict__ Ahi, const bf16* __restrict__ Alo,
    const bf16* __restrict__ Bhi, const bf16* __restrict__ Blo,
    int m0, int n0, int K, int k0)
{
    const int r  = tid >> 1;
    const int cg = (tid & 1) * 4;
    const uint32_t sb = sdata + buf * STG_B;
    const size_t ao = (size_t)(m0 + r) * K + k0 + cg * 8;
    const size_t bo = (size_t)(n0 + r) * K + k0 + cg * 8;
#pragma unroll
    for (int c = 0; c < 4; c++) {
        const uint32_t off = r * 128 + (cg + c) * 16;
        const uint32_t sw = off ^ ((off >> 3) & 0x70);   // == row*128 + ((col16^(row&7))*16)
        cpa16(sb + sw,              Ahi + ao + c * 8);
        cpa16(sb + TILE_B + sw,     Alo + ao + c * 8);
        cpa16(sb + 2 * TILE_B + sw, Bhi + bo + c * 8);
        cpa16(sb + 3 * TILE_B + sw, Blo + bo + c * 8);
    }
    asm volatile("cp.async.commit_group;" ::: "memory");
}

__global__ __launch_bounds__(256, 1)
void mma_gemm(const bf16* __restrict__ Ahi, const bf16* __restrict__ Alo,
              const bf16* __restrict__ Bhi, const bf16* __restrict__ Blo,
              const float* __restrict__ bias, const float* __restrict__ R,
              float* __restrict__ C, bf16* __restrict__ Chi, bf16* __restrict__ Clo,
              int M, int N, int K, int mode, float scale)
{
    extern __shared__ char smem[];
    const uint32_t sdata = smem_u32(smem);
    const int tid = threadIdx.x;
    const int wid = tid >> 5, lane = tid & 31;
    const int warp_m = wid & 1;          // 2 warps along M (64 rows each)
    const int warp_n = wid >> 1;         // 4 warps along N (32 cols each)
    const int m0 = blockIdx.y * GB_M, n0 = blockIdx.x * GB_N;

    // ldmatrix per-lane address components
    const int aRow   = lane & 15;            // row within 16-row tile
    const int aChunk = lane >> 4;            // +0/+1 16B chunk
    const int bRow   = (lane & 7) + ((lane >> 4) << 3);  // n within 16
    const int bChunk = (lane >> 3) & 1;

    float acc[4][4][4];
#pragma unroll
    for (int i = 0; i < 4; i++)
#pragma unroll
        for (int j = 0; j < 4; j++)
#pragma unroll
            for (int t = 0; t < 4; t++) acc[i][j][t] = 0.f;

    const int NK = K / GB_K;
    gemm_load_stage(tid, sdata, 0, Ahi, Alo, Bhi, Blo, m0, n0, K, 0);

    for (int j = 0; j < NK; j++) {
        const int p = j & 1;
        if (j + 1 < NK) {
            gemm_load_stage(tid, sdata, 1 - p, Ahi, Alo, Bhi, Blo, m0, n0, K, (j + 1) * GB_K);
            asm volatile("cp.async.wait_group 1;" ::: "memory");
        } else {
            asm volatile("cp.async.wait_group 0;" ::: "memory");
        }
        __syncthreads();

        const uint32_t sb  = sdata + p * STG_B;
        const uint32_t sAh = sb;
        const uint32_t sAl = sb + TILE_B;
        const uint32_t sBh = sb + 2 * TILE_B;
        const uint32_t sBl = sb + 3 * TILE_B;

#pragma unroll
        for (int s = 0; s < 4; s++) {       // 4 x k16 steps within BK=64
            const int c0 = 2 * s;
            uint32_t bfh[4][2], bfl[4][2];
#pragma unroll
            for (int bt = 0; bt < 2; bt++) {   // each ldsm4 covers two n8 tiles
                const int nrow = warp_n * 32 + bt * 16 + bRow;
                const uint32_t off = (uint32_t)nrow * 128 +
                                     (uint32_t)(((c0 + bChunk) ^ (nrow & 7)) * 16);
                ldsm4(bfh[2*bt][0], bfh[2*bt][1], bfh[2*bt+1][0], bfh[2*bt+1][1], sBh + off);
                ldsm4(bfl[2*bt][0], bfl[2*bt][1], bfl[2*bt+1][0], bfl[2*bt+1][1], sBl + off);
            }
#pragma unroll
            for (int mt = 0; mt < 4; mt++) {
                const int arow = warp_m * 64 + mt * 16 + aRow;
                const uint32_t off = (uint32_t)arow * 128 +
                                     (uint32_t)(((c0 + aChunk) ^ (arow & 7)) * 16);
                uint32_t ah[4], al[4];
                ldsm4(ah[0], ah[1], ah[2], ah[3], sAh + off);
                ldsm4(al[0], al[1], al[2], al[3], sAl + off);
#pragma unroll
                for (int nt = 0; nt < 4; nt++) {
                    mma_bf16(acc[mt][nt], ah, bfh[nt]);
                    mma_bf16(acc[mt][nt], al, bfh[nt]);
                    mma_bf16(acc[mt][nt], ah, bfl[nt]);
                }
            }
        }
        __syncthreads();
    }

    // ---------------- epilogue (from registers) ----------------
    const int rbase = lane >> 2;            // 0..7
    const int cbase = (lane & 3) * 2;       // 0,2,4,6
#pragma unroll
    for (int mt = 0; mt < 4; mt++) {
#pragma unroll
        for (int half = 0; half < 2; half++) {     // c0/c1 vs c2/c3 (row, row+8)
            const int m = m0 + warp_m * 64 + mt * 16 + rbase + half * 8;
            const int bidx = m >> 12, srow = m & (SS - 1);
#pragma unroll
            for (int nt = 0; nt < 4; nt++) {
                const int n = n0 + warp_n * 32 + nt * 8 + cbase;
                const float v0r = acc[mt][nt][half * 2 + 0];
                const float v1r = acc[mt][nt][half * 2 + 1];
                if (mode == EP_QKV) {
                    const int hh = n >> 6, d0 = n & 63;
                    float2 vv;
                    vv.x = (v0r + bias[n])     * scale;
                    vv.y = (v1r + bias[n + 1]) * scale;
                    *(float2*)&C[(((size_t)(bidx * NHH + hh)) * SS + srow) * DH + d0] = vv;
                } else if (mode == EP_RES) {
                    const size_t o = (size_t)m * N + n;
                    const float2 rv = *(const float2*)&R[o];
                    float2 vv;
                    vv.x = v0r + bias[n]     + rv.x;
                    vv.y = v1r + bias[n + 1] + rv.y;
                    *(float2*)&C[o] = vv;
                } else { // EP_GELU_BF
                    float v0 = v0r + bias[n];
                    float v1 = v1r + bias[n + 1];
                    v0 = 0.5f * v0 * (1.f + erff(v0 * 0.70710678118654752f));
                    v1 = 0.5f * v1 * (1.f + erff(v1 * 0.70710678118654752f));
                    const bf16 h0 = __float2bfloat16(v0), h1 = __float2bfloat16(v1);
                    const bf16 l0 = __float2bfloat16(v0 - __bfloat162float(h0));
                    const bf16 l1 = __float2bfloat16(v1 - __bfloat162float(h1));
                    const size_t o = (size_t)m * N + n;
                    *(__nv_bfloat162*)&Chi[o] = __nv_bfloat162(h0, h1);
                    *(__nv_bfloat162*)&Clo[o] = __nv_bfloat162(l0, l1);
                }
            }
        }
    }
}

// ---------------- elementwise convert fp32 -> bf16 hi/lo --------------------
__global__ __launch_bounds__(256)
void convert_hilo(const float* __restrict__ X, bf16* __restrict__ H, bf16* __restrict__ L, int n4)
{
    const int i = blockIdx.x * 256 + threadIdx.x;
    if (i >= n4) return;
    const float4 v = ((const float4*)X)[i];
    bf16 h0 = __float2bfloat16(v.x), h1 = __float2bfloat16(v.y);
    bf16 h2 = __float2bfloat16(v.z), h3 = __float2bfloat16(v.w);
    ((__nv_bfloat162*)H)[i * 2 + 0] = __nv_bfloat162(h0, h1);
    ((__nv_bfloat162*)H)[i * 2 + 1] = __nv_bfloat162(h2, h3);
    ((__nv_bfloat162*)L)[i * 2 + 0] = __nv_bfloat162(
        __float2bfloat16(v.x - __bfloat162float(h0)), __float2bfloat16(v.y - __bfloat162float(h1)));
    ((__nv_bfloat162*)L)[i * 2 + 1] = __nv_bfloat162(
        __float2bfloat16(v.z - __bfloat162float(h2)), __float2bfloat16(v.w - __bfloat162float(h3)));
}

// ---------------- transpose fp32 [K,N] -> bf16 hi/lo [N,K] ------------------
__global__ __launch_bounds__(256)
void transpose_hilo(const float* __restrict__ W, bf16* __restrict__ Th, bf16* __restrict__ Tl,
                    int K, int N)
{
    __shared__ float t[32][33];
    const int nb = blockIdx.x * 32, kb = blockIdx.y * 32;
    const int tx = threadIdx.x & 31, ty = (threadIdx.x >> 5) * 4;
#pragma unroll
    for (int i = 0; i < 4; i++)
        t[ty + i][tx] = W[(size_t)(kb + ty + i) * N + nb + tx];
    __syncthreads();
#pragma unroll
    for (int i = 0; i < 4; i++) {
        const float v = t[tx][ty + i];
        const bf16 hv = __float2bfloat16(v);
        Th[(size_t)(nb + ty + i) * K + kb + tx] = hv;
        Tl[(size_t)(nb + ty + i) * K + kb + tx] = __float2bfloat16(v - __bfloat162float(hv));
    }
}

// ---------------- local (banded) attention ----------------------------------
#define LOC_SMEM ((384*64*2 + 32*64*2 + 384 + 32) * sizeof(float))

__global__ __launch_bounds__(128)
void local_attn(const float* __restrict__ q, const float* __restrict__ k,
                const float* __restrict__ v, const float* __restrict__ am,
                bf16* __restrict__ ctx_hi, bf16* __restrict__ ctx_lo)
{
    extern __shared__ float sm[];
    float* ks  = sm;
    float* vs  = ks + 384 * 64;
    float* gks = vs + 384 * 64;
    float* gvs = gks + 32 * 64;
    float* ams = gvs + 32 * 64;

    const int c = blockIdx.x, bh = blockIdx.y;
    const int b = bh / NHH, h = bh % NHH;
    const int tid = threadIdx.x;
    const float* kb = k + (size_t)bh * SS * DH;
    const float* vb = v + (size_t)bh * SS * DH;
    const int base = c * WW - WW;

    for (int i = tid; i < 384 * 64; i += 128) {
        const int j = i >> 6, d = i & 63;
        const int kp = base + j;
        const bool in = (kp >= 0 && kp < SS);
        ks[i] = in ? kb[(size_t)kp * DH + d] : 0.f;
        vs[i] = in ? vb[(size_t)kp * DH + d] : 0.f;
    }
    for (int i = tid; i < 32 * 64; i += 128) { gks[i] = kb[i]; gvs[i] = vb[i]; }
    for (int j = tid; j < 384; j += 128) {
        const int kp = base + j;
        ams[j] = (kp >= 0 && kp < SS) ? am[b * SS + kp] : 0.f;
    }
    if (tid < 32) ams[384 + tid] = am[b * SS + tid];
    __syncthreads();

    const int s = c * WW + tid;
    float qr[64];
    const float* qp = q + ((size_t)bh * SS + s) * DH;
#pragma unroll
    for (int d = 0; d < 64; d += 4) {
        float4 t = *(const float4*)&qp[d];
        qr[d] = t.x; qr[d + 1] = t.y; qr[d + 2] = t.z; qr[d + 3] = t.w;
    }

    float mval = -1e30f, l = 0.f;
    float acc[64];
#pragma unroll
    for (int d = 0; d < 64; d++) acc[d] = 0.f;

    for (int j = 0; j < 384; j++) {
        const int kp = base + j;
        const int dlt = kp - s;
        if (dlt < -WW || dlt > WW || kp < NGG || kp >= SS) continue;
        const float* kr = &ks[j * 64];
        float s0 = 0.f, s1 = 0.f, s2 = 0.f, s3 = 0.f;
#pragma unroll
        for (int d = 0; d < 64; d += 4) {
            s0 += qr[d]     * kr[d];
            s1 += qr[d + 1] * kr[d + 1];
            s2 += qr[d + 2] * kr[d + 2];
            s3 += qr[d + 3] * kr[d + 3];
        }
        const float sc = (s0 + s1) + (s2 + s3) + ams[j];
        const float mn = fmaxf(mval, sc);
        const float corr = __expf(mval - mn);
        const float p = __expf(sc - mn);
        l = l * corr + p;
        const float* vr = &vs[j * 64];
#pragma unroll
        for (int d = 0; d < 64; d++) acc[d] = acc[d] * corr + p * vr[d];
        mval = mn;
    }
    for (int j = 0; j < 32; j++) {
        const float* kr = &gks[j * 64];
        float s0 = 0.f, s1 = 0.f, s2 = 0.f, s3 = 0.f;
#pragma unroll
        for (int d = 0; d < 64; d += 4) {
            s0 += qr[d]     * kr[d];
            s1 += qr[d + 1] * kr[d + 1];
            s2 += qr[d + 2] * kr[d + 2];
            s3 += qr[d + 3] * kr[d + 3];
        }
        const float sc = (s0 + s1) + (s2 + s3) + ams[384 + j];
        const float mn = fmaxf(mval, sc);
        const float corr = __expf(mval - mn);
        const float p = __expf(sc - mn);
        l = l * corr + p;
        const float* vr = &gvs[j * 64];
#pragma unroll
        for (int d = 0; d < 64; d++) acc[d] = acc[d] * corr + p * vr[d];
        mval = mn;
    }

    if (s >= NGG) {
        const float inv = 1.f / l;
        const size_t ob = ((size_t)(b * SS + s)) * DDIM + h * DH;
#pragma unroll
        for (int d = 0; d < 64; d++) {
            const float val = acc[d] * inv;
            const bf16 hv = __float2bfloat16(val);
            ctx_hi[ob + d] = hv;
            ctx_lo[ob + d] = __float2bfloat16(val - __bfloat162float(hv));
        }
    }
}

// ---------------- global-row attention --------------------------------------
__global__ __launch_bounds__(128)
void global_attn(const float* __restrict__ q, const float* __restrict__ k,
                 const float* __restrict__ v, const float* __restrict__ am,
                 bf16* __restrict__ ctx_hi, bf16* __restrict__ ctx_lo)
{
    __shared__ float lg[SS];
    __shared__ float qs[64];
    __shared__ float red[128];

    const int g = blockIdx.x, bh = blockIdx.y;
    const int b = bh / NHH, h = bh % NHH;
    const int tid = threadIdx.x;

    if (tid < 64) qs[tid] = q[((size_t)bh * SS + g) * DH + tid];
    __syncthreads();

    const float* kb = k + (size_t)bh * SS * DH;
    for (int s = tid; s < SS; s += 128) {
        const float4* kr = (const float4*)&kb[(size_t)s * DH];
        float s0 = 0.f, s1 = 0.f, s2 = 0.f, s3 = 0.f;
#pragma unroll
        for (int d4 = 0; d4 < 16; d4++) {
            const float4 kv = kr[d4];
            s0 += qs[d4 * 4 + 0] * kv.x;
            s1 += qs[d4 * 4 + 1] * kv.y;
            s2 += qs[d4 * 4 + 2] * kv.z;
            s3 += qs[d4 * 4 + 3] * kv.w;
        }
        lg[s] = (s0 + s1) + (s2 + s3) + am[b * SS + s];
    }
    __syncthreads();

    float mx = -1e30f;
    for (int s = tid; s < SS; s += 128) mx = fmaxf(mx, lg[s]);
    red[tid] = mx;
    __syncthreads();
    for (int st = 64; st > 0; st >>= 1) {
        if (tid < st) red[tid] = fmaxf(red[tid], red[tid + st]);
        __syncthreads();
    }
    mx = red[0];
    __syncthreads();

    float sum = 0.f;
    for (int s = tid; s < SS; s += 128) {
        const float e = __expf(lg[s] - mx);
        lg[s] = e;
        sum += e;
    }
    red[tid] = sum;
    __syncthreads();
    for (int st = 64; st > 0; st >>= 1) {
        if (tid < st) red[tid] += red[tid + st];
        __syncthreads();
    }
    const float inv = 1.f / red[0];
    __syncthreads();

    const float* vb = v + (size_t)bh * SS * DH;
    const int d = tid & 63, half = tid >> 6;
    float acc = 0.f;
    const int s0 = half * (SS / 2), s1 = s0 + SS / 2;
    for (int s = s0; s < s1; s++)
        acc += lg[s] * vb[(size_t)s * DH + d];
    red[tid] = acc;
    __syncthreads();
    if (tid < 64) {
        const float val = (red[tid] + red[tid + 64]) * inv;
        const size_t ob = ((size_t)(b * SS + g)) * DDIM + h * DH + d;
        const bf16 hv = __float2bfloat16(val);
        ctx_hi[ob] = hv;
        ctx_lo[ob] = __float2bfloat16(val - __bfloat162float(hv));
    }
}

// ---------------- layernorm (optional bf16 hi/lo side output) ---------------
__global__ __launch_bounds__(256)
void layernorm_k(const float* __restrict__ X, const float* __restrict__ gw,
                 const float* __restrict__ bw, float* __restrict__ Y,
                 bf16* __restrict__ Yh, bf16* __restrict__ Yl)
{
    __shared__ float xs[DDIM];
    __shared__ float red[256];
    const int row = blockIdx.x, tid = threadIdx.x;
    const float* xp = X + (size_t)row * DDIM;

    float sum = 0.f;
    for (int i = tid; i < DDIM; i += 256) { const float t = xp[i]; xs[i] = t; sum += t; }
    red[tid] = sum;
    __syncthreads();
    for (int st = 128; st > 0; st >>= 1) {
        if (tid < st) red[tid] += red[tid + st];
        __syncthreads();
    }
    const float mu = red[0] * (1.f / DDIM);
    __syncthreads();

    float vsum = 0.f;
    for (int i = tid; i < DDIM; i += 256) { const float d = xs[i] - mu; vsum += d * d; }
    red[tid] = vsum;
    __syncthreads();
    for (int st = 128; st > 0; st >>= 1) {
        if (tid < st) red[tid] += red[tid + st];
        __syncthreads();
    }
    const float rstd = rsqrtf(red[0] * (1.f / DDIM) + 1e-12f);
    for (int i = tid; i < DDIM; i += 256) {
        const float val = (xs[i] - mu) * rstd * gw[i] + bw[i];
        Y[(size_t)row * DDIM + i] = val;
        if (Yh) {
            const bf16 hv = __float2bfloat16(val);
            Yh[(size_t)row * DDIM + i] = hv;
            Yl[(size_t)row * DDIM + i] = __float2bfloat16(val - __bfloat162float(hv));
        }
    }
}

// ---------------- launch ----------------------------------------------------
extern "C" void kernel_launch(void* const* d_in, const int* in_sizes, int n_in,
                              void* d_out, int out_size)
{
    const float* h    = (const float*)d_in[0];
    const float* am   = (const float*)d_in[1];
    const float* Wq   = (const float*)d_in[2];
    const float* bq   = (const float*)d_in[3];
    const float* Wk   = (const float*)d_in[4];
    const float* bk   = (const float*)d_in[5];
    const float* Wv   = (const float*)d_in[6];
    const float* bv   = (const float*)d_in[7];
    const float* Wo   = (const float*)d_in[8];
    const float* bo   = (const float*)d_in[9];
    const float* ln1g = (const float*)d_in[10];
    const float* ln1b = (const float*)d_in[11];
    const float* Wi   = (const float*)d_in[12];
    const float* bi   = (const float*)d_in[13];
    const float* Wo2  = (const float*)d_in[14];
    const float* bo2  = (const float*)d_in[15];
    const float* ln2g = (const float*)d_in[16];
    const float* ln2b = (const float*)d_in[17];

    float *q, *k, *v, *x1, *attn, *x2;
    bf16 *h_hi, *h_lo, *ctx_hi, *ctx_lo, *at_hi, *at_lo, *in_hi, *in_lo;
    bf16 *wqt_hi, *wqt_lo, *wkt_hi, *wkt_lo, *wvt_hi, *wvt_lo, *wot_hi, *wot_lo;
    bf16 *wit_hi, *wit_lo, *wo2t_hi, *wo2t_lo;
    cudaGetSymbolAddress((void**)&q,    g_q);
    cudaGetSymbolAddress((void**)&k,    g_k);
    cudaGetSymbolAddress((void**)&v,    g_v);
    cudaGetSymbolAddress((void**)&x1,   g_x1);
    cudaGetSymbolAddress((void**)&attn, g_attn);
    cudaGetSymbolAddress((void**)&x2,   g_x2);
    cudaGetSymbolAddress((void**)&h_hi, g_h_hi);
    cudaGetSymbolAddress((void**)&h_lo, g_h_lo);
    cudaGetSymbolAddress((void**)&ctx_hi, g_ctx_hi);
    cudaGetSymbolAddress((void**)&ctx_lo, g_ctx_lo);
    cudaGetSymbolAddress((void**)&at_hi, g_at_hi);
    cudaGetSymbolAddress((void**)&at_lo, g_at_lo);
    cudaGetSymbolAddress((void**)&in_hi, g_in_hi);
    cudaGetSymbolAddress((void**)&in_lo, g_in_lo);
    cudaGetSymbolAddress((void**)&wqt_hi, g_wqt_hi);
    cudaGetSymbolAddress((void**)&wqt_lo, g_wqt_lo);
    cudaGetSymbolAddress((void**)&wkt_hi, g_wkt_hi);
    cudaGetSymbolAddress((void**)&wkt_lo, g_wkt_lo);
    cudaGetSymbolAddress((void**)&wvt_hi, g_wvt_hi);
    cudaGetSymbolAddress((void**)&wvt_lo, g_wvt_lo);
    cudaGetSymbolAddress((void**)&wot_hi, g_wot_hi);
    cudaGetSymbolAddress((void**)&wot_lo, g_wot_lo);
    cudaGetSymbolAddress((void**)&wit_hi, g_wit_hi);
    cudaGetSymbolAddress((void**)&wit_lo, g_wit_lo);
    cudaGetSymbolAddress((void**)&wo2t_hi, g_wo2t_hi);
    cudaGetSymbolAddress((void**)&wo2t_lo, g_wo2t_lo);

    cudaFuncSetAttribute(local_attn, cudaFuncAttributeMaxDynamicSharedMemorySize, (int)LOC_SMEM);
    cudaFuncSetAttribute(mma_gemm, cudaFuncAttributeMaxDynamicSharedMemorySize, GEMM_SMEM);

    // --- prepare bf16 hi/lo operands ---
    convert_hilo<<<(MM * DDIM / 4 + 255) / 256, 256>>>(h, h_hi, h_lo, MM * DDIM / 4);
    transpose_hilo<<<dim3(DDIM / 32, DDIM / 32), 256>>>(Wq,  wqt_hi,  wqt_lo,  DDIM, DDIM);
    transpose_hilo<<<dim3(DDIM / 32, DDIM / 32), 256>>>(Wk,  wkt_hi,  wkt_lo,  DDIM, DDIM);
    transpose_hilo<<<dim3(DDIM / 32, DDIM / 32), 256>>>(Wv,  wvt_hi,  wvt_lo,  DDIM, DDIM);
    transpose_hilo<<<dim3(DDIM / 32, DDIM / 32), 256>>>(Wo,  wot_hi,  wot_lo,  DDIM, DDIM);
    transpose_hilo<<<dim3(FF / 32,   DDIM / 32), 256>>>(Wi,  wit_hi,  wit_lo,  DDIM, FF);   // [3072][768]
    transpose_hilo<<<dim3(DDIM / 32, FF / 32),   256>>>(Wo2, wo2t_hi, wo2t_lo, FF, DDIM);   // [768][3072]

    const dim3 gD(DDIM / GB_N, MM / GB_M);   // (6, 64)
    const dim3 gF(FF / GB_N,   MM / GB_M);   // (24, 64)

    // --- QKV projections ---
    mma_gemm<<<gD, 256, GEMM_SMEM>>>(h_hi, h_lo, wqt_hi, wqt_lo, bq, nullptr, q, nullptr, nullptr,
                                     MM, DDIM, DDIM, EP_QKV, 0.125f);
    mma_gemm<<<gD, 256, GEMM_SMEM>>>(h_hi, h_lo, wkt_hi, wkt_lo, bk, nullptr, k, nullptr, nullptr,
                                     MM, DDIM, DDIM, EP_QKV, 1.f);
    mma_gemm<<<gD, 256, GEMM_SMEM>>>(h_hi, h_lo, wvt_hi, wvt_lo, bv, nullptr, v, nullptr, nullptr,
                                     MM, DDIM, DDIM, EP_QKV, 1.f);

    // --- attention (writes ctx directly as bf16 hi/lo) ---
    local_attn<<<dim3(CC, BB * NHH), 128, LOC_SMEM>>>(q, k, v, am, ctx_hi, ctx_lo);
    global_attn<<<dim3(NGG, BB * NHH), 128>>>(q, k, v, am, ctx_hi, ctx_lo);

    // --- output projection + residual, LN1 (LN emits bf16 hi/lo too) ---
    mma_gemm<<<gD, 256, GEMM_SMEM>>>(ctx_hi, ctx_lo, wot_hi, wot_lo, bo, h, x1, nullptr, nullptr,
                                     MM, DDIM, DDIM, EP_RES, 1.f);
    layernorm_k<<<MM, 256>>>(x1, ln1g, ln1b, attn, at_hi, at_lo);

    // --- FFN ---
    mma_gemm<<<gF, 256, GEMM_SMEM>>>(at_hi, at_lo, wit_hi, wit_lo, bi, nullptr, nullptr, in_hi, in_lo,
                                     MM, FF, DDIM, EP_GELU_BF, 1.f);
    mma_gemm<<<gD, 256, GEMM_SMEM>>>(in_hi, in_lo, wo2t_hi, wo2t_lo, bo2, attn, x2, nullptr, nullptr,
                                     MM, DDIM, FF, EP_RES, 1.f);
    layernorm_k<<<MM, 256>>>(x2, ln2g, ln2b, (float*)d_out, nullptr, nullptr);
}

// round 10
// speedup vs baseline: 2.0687x; 1.6965x over previous
#include <cuda_runtime.h>
#include <cuda_bf16.h>
#include <math.h>
#include <stdint.h>

// ---------------- problem constants ----------------
#define BB   2
#define SS   4096
#define DDIM 768
#define FF   3072
#define NHH  12
#define DH   64
#define WW   128
#define NGG  32
#define CC   (SS/WW)      // 32 chunks
#define MM   (BB*SS)      // 8192 rows

typedef __nv_bfloat16 bf16;

// ---------------- scratch (static device arrays; no allocs allowed) ----------
__device__ float g_q   [BB*NHH*SS*DH];
__device__ float g_k   [BB*NHH*SS*DH];
__device__ float g_v   [BB*NHH*SS*DH];
__device__ float g_x1  [MM*DDIM];
__device__ float g_attn[MM*DDIM];
__device__ float g_x2  [MM*DDIM];

__device__ bf16 g_h_hi [MM*DDIM];
__device__ bf16 g_h_lo [MM*DDIM];
__device__ bf16 g_ctx_hi[MM*DDIM];
__device__ bf16 g_ctx_lo[MM*DDIM];
__device__ bf16 g_at_hi[MM*DDIM];
__device__ bf16 g_at_lo[MM*DDIM];
__device__ bf16 g_in_hi[(size_t)MM*FF];
__device__ bf16 g_in_lo[(size_t)MM*FF];

__device__ bf16 g_wqt_hi[DDIM*DDIM], g_wqt_lo[DDIM*DDIM];
__device__ bf16 g_wkt_hi[DDIM*DDIM], g_wkt_lo[DDIM*DDIM];
__device__ bf16 g_wvt_hi[DDIM*DDIM], g_wvt_lo[DDIM*DDIM];
__device__ bf16 g_wot_hi[DDIM*DDIM], g_wot_lo[DDIM*DDIM];
__device__ bf16 g_wit_hi[DDIM*FF],   g_wit_lo[DDIM*FF];    // [3072][768]
__device__ bf16 g_wo2t_hi[DDIM*FF],  g_wo2t_lo[DDIM*FF];   // [768][3072]

// ================= helpers =================
__device__ __forceinline__ uint32_t smem_u32(const void* p) {
    uint32_t a;
    asm("{ .reg .u64 t; cvta.to.shared.u64 t, %1; cvt.u32.u64 %0, t; }" : "=r"(a) : "l"(p));
    return a;
}
__device__ __forceinline__ void cpa16(uint32_t s, const void* g) {
    asm volatile("cp.async.cg.shared.global [%0], [%1], 16;\n" :: "r"(s), "l"(g));
}
__device__ __forceinline__ void ldsm4(uint32_t& r0, uint32_t& r1, uint32_t& r2, uint32_t& r3,
                                      uint32_t addr) {
    asm volatile("ldmatrix.sync.aligned.m8n8.x4.shared.b16 {%0,%1,%2,%3}, [%4];"
                 : "=r"(r0), "=r"(r1), "=r"(r2), "=r"(r3) : "r"(addr));
}
__device__ __forceinline__ void mma_bf16(float* c, const uint32_t* a, const uint32_t* b) {
    asm volatile("mma.sync.aligned.m16n8k16.row.col.f32.bf16.bf16.f32 "
                 "{%0,%1,%2,%3}, {%4,%5,%6,%7}, {%8,%9}, {%0,%1,%2,%3};"
                 : "+f"(c[0]), "+f"(c[1]), "+f"(c[2]), "+f"(c[3])
                 : "r"(a[0]), "r"(a[1]), "r"(a[2]), "r"(a[3]), "r"(b[0]), "r"(b[1]));
}

// ================= bf16 split GEMM: C[M,N] = (Ahi+Alo)(Bhi+Blo)^T ===========
// A: [M,K] bf16 hi/lo. B: [N,K] bf16 hi/lo (pre-transposed weights).
// Tile 128x128, K-chunk 32, 3-stage cp.async pipeline, 2 CTAs/SM.
// smem layout per matrix: row pairs packed into 128B lines,
//   slot16(r,c) = ((r&1)*4 + c) ^ ((r>>1)&7);  off = (r>>1)*128 + slot16*16
// -> conflict-free ldmatrix (8 lanes cover slots {c^p} U {4+(c^p)} = 0..7).
#define GB_M 128
#define GB_N 128
#define GB_K 32
#define MAT_B (128*64)         // 8 KB per matrix per stage
#define STG_B (4*MAT_B)        // 32 KB: Ahi,Alo,Bhi,Blo
#define NSTG  3
#define GEMM_SMEM (NSTG*STG_B) // 96 KB

#define EP_QKV     0   // write permuted [b][h][s][d] fp32, (val+bias)*scale
#define EP_RES     1   // fp32 = val + bias + R
#define EP_GELU_BF 2   // bf16 hi/lo of gelu(val+bias)

__device__ __forceinline__ uint32_t sw_off(int row, int c) {
    return ((uint32_t)(row >> 1) * 128) +
           (uint32_t)(((((row & 1) * 4) + c) ^ ((row >> 1) & 7)) * 16);
}

__device__ __forceinline__ void gemm_load_stage(
    int tid, uint32_t sdata, int buf,
    const bf16* __restrict__ Ahi, const bf16* __restrict__ Alo,
    const bf16* __restrict__ Bhi, const bf16* __restrict__ Blo,
    int m0, int n0, int K, int k0)
{
    const int r  = tid >> 1;           // 0..127
    const int cg = (tid & 1) * 2;      // 0 or 2 (two col16 each)
    const uint32_t sb = sdata + buf * STG_B;
    const size_t ao = (size_t)(m0 + r) * K + k0;
    const size_t bo = (size_t)(n0 + r) * K + k0;
#pragma unroll
    for (int cc = 0; cc < 2; cc++) {
        const int c = cg + cc;
        const uint32_t off = sw_off(r, c);
        cpa16(sb + off,             Ahi + ao + c * 8);
        cpa16(sb + MAT_B + off,     Alo + ao + c * 8);
        cpa16(sb + 2 * MAT_B + off, Bhi + bo + c * 8);
        cpa16(sb + 3 * MAT_B + off, Blo + bo + c * 8);
    }
    asm volatile("cp.async.commit_group;" ::: "memory");
}

__global__ __launch_bounds__(256, 2)
void mma_gemm(const bf16* __restrict__ Ahi, const bf16* __restrict__ Alo,
              const bf16* __restrict__ Bhi, const bf16* __restrict__ Blo,
              const float* __restrict__ bias, const float* __restrict__ R,
              float* __restrict__ C, bf16* __restrict__ Chi, bf16* __restrict__ Clo,
              int M, int N, int K, int mode, float scale)
{
    extern __shared__ char smem[];
    const uint32_t sdata = smem_u32(smem);
    const int tid = threadIdx.x;
    const int wid = tid >> 5, lane = tid & 31;
    const int warp_m = wid & 1;          // 2 warps along M (64 rows each)
    const int warp_n = wid >> 1;         // 4 warps along N (32 cols each)
    const int m0 = blockIdx.y * GB_M, n0 = blockIdx.x * GB_N;

    // ldmatrix per-lane address components
    const int aRow   = lane & 15;
    const int aChunk = lane >> 4;                        // +0/+1 col16
    const int bRow   = (lane & 7) + ((lane >> 4) << 3);  // n within 16
    const int bChunk = (lane >> 3) & 1;

    float acc[4][4][4];
#pragma unroll
    for (int i = 0; i < 4; i++)
#pragma unroll
        for (int j = 0; j < 4; j++)
#pragma unroll
            for (int t = 0; t < 4; t++) acc[i][j][t] = 0.f;

    const int NK = K / GB_K;

    // prologue: stages 0..NSTG-2
    gemm_load_stage(tid, sdata, 0, Ahi, Alo, Bhi, Blo, m0, n0, K, 0);
    gemm_load_stage(tid, sdata, 1, Ahi, Alo, Bhi, Blo, m0, n0, K, GB_K);

    for (int j = 0; j < NK; j++) {
        if (j + NSTG - 1 < NK)
            gemm_load_stage(tid, sdata, (j + NSTG - 1) % NSTG,
                            Ahi, Alo, Bhi, Blo, m0, n0, K, (j + NSTG - 1) * GB_K);
        const int rem = NK - 1 - j;
        if (rem >= 2)      asm volatile("cp.async.wait_group 2;" ::: "memory");
        else if (rem == 1) asm volatile("cp.async.wait_group 1;" ::: "memory");
        else               asm volatile("cp.async.wait_group 0;" ::: "memory");
        __syncthreads();

        const uint32_t sb  = sdata + (j % NSTG) * STG_B;
        const uint32_t sAh = sb;
        const uint32_t sAl = sb + MAT_B;
        const uint32_t sBh = sb + 2 * MAT_B;
        const uint32_t sBl = sb + 3 * MAT_B;

#pragma unroll
        for (int s = 0; s < 2; s++) {       // 2 x k16 steps within BK=32
            const int c0 = 2 * s;
            uint32_t bfh[4][2], bfl[4][2];
#pragma unroll
            for (int bt = 0; bt < 2; bt++) {
                const int nrow = warp_n * 32 + bt * 16 + bRow;
                const uint32_t off = sw_off(nrow, c0 + bChunk);
                ldsm4(bfh[2*bt][0], bfh[2*bt][1], bfh[2*bt+1][0], bfh[2*bt+1][1], sBh + off);
                ldsm4(bfl[2*bt][0], bfl[2*bt][1], bfl[2*bt+1][0], bfl[2*bt+1][1], sBl + off);
            }
#pragma unroll
            for (int mt = 0; mt < 4; mt++) {
                const int arow = warp_m * 64 + mt * 16 + aRow;
                const uint32_t off = sw_off(arow, c0 + aChunk);
                uint32_t ah[4], al[4];
                ldsm4(ah[0], ah[1], ah[2], ah[3], sAh + off);
                ldsm4(al[0], al[1], al[2], al[3], sAl + off);
#pragma unroll
                for (int nt = 0; nt < 4; nt++) {
                    mma_bf16(acc[mt][nt], ah, bfh[nt]);
                    mma_bf16(acc[mt][nt], al, bfh[nt]);
                    mma_bf16(acc[mt][nt], ah, bfl[nt]);
                }
            }
        }
        __syncthreads();
    }

    // ---------------- epilogue (from registers) ----------------
    const int rbase = lane >> 2;            // 0..7
    const int cbase = (lane & 3) * 2;       // 0,2,4,6
#pragma unroll
    for (int mt = 0; mt < 4; mt++) {
#pragma unroll
        for (int half = 0; half < 2; half++) {     // c0/c1 vs c2/c3 (row, row+8)
            const int m = m0 + warp_m * 64 + mt * 16 + rbase + half * 8;
            const int bidx = m >> 12, srow = m & (SS - 1);
#pragma unroll
            for (int nt = 0; nt < 4; nt++) {
                const int n = n0 + warp_n * 32 + nt * 8 + cbase;
                const float v0r = acc[mt][nt][half * 2 + 0];
                const float v1r = acc[mt][nt][half * 2 + 1];
                if (mode == EP_QKV) {
                    const int hh = n >> 6, d0 = n & 63;
                    float2 vv;
                    vv.x = (v0r + bias[n])     * scale;
                    vv.y = (v1r + bias[n + 1]) * scale;
                    *(float2*)&C[(((size_t)(bidx * NHH + hh)) * SS + srow) * DH + d0] = vv;
                } else if (mode == EP_RES) {
                    const size_t o = (size_t)m * N + n;
                    const float2 rv = *(const float2*)&R[o];
                    float2 vv;
                    vv.x = v0r + bias[n]     + rv.x;
                    vv.y = v1r + bias[n + 1] + rv.y;
                    *(float2*)&C[o] = vv;
                } else { // EP_GELU_BF
                    float v0 = v0r + bias[n];
                    float v1 = v1r + bias[n + 1];
                    v0 = 0.5f * v0 * (1.f + erff(v0 * 0.70710678118654752f));
                    v1 = 0.5f * v1 * (1.f + erff(v1 * 0.70710678118654752f));
                    const bf16 h0 = __float2bfloat16(v0), h1 = __float2bfloat16(v1);
                    const bf16 l0 = __float2bfloat16(v0 - __bfloat162float(h0));
                    const bf16 l1 = __float2bfloat16(v1 - __bfloat162float(h1));
                    const size_t o = (size_t)m * N + n;
                    *(__nv_bfloat162*)&Chi[o] = __nv_bfloat162(h0, h1);
                    *(__nv_bfloat162*)&Clo[o] = __nv_bfloat162(l0, l1);
                }
            }
        }
    }
}

// ---------------- elementwise convert fp32 -> bf16 hi/lo --------------------
__global__ __launch_bounds__(256)
void convert_hilo(const float* __restrict__ X, bf16* __restrict__ H, bf16* __restrict__ L, int n4)
{
    const int i = blockIdx.x * 256 + threadIdx.x;
    if (i >= n4) return;
    const float4 v = ((const float4*)X)[i];
    bf16 h0 = __float2bfloat16(v.x), h1 = __float2bfloat16(v.y);
    bf16 h2 = __float2bfloat16(v.z), h3 = __float2bfloat16(v.w);
    ((__nv_bfloat162*)H)[i * 2 + 0] = __nv_bfloat162(h0, h1);
    ((__nv_bfloat162*)H)[i * 2 + 1] = __nv_bfloat162(h2, h3);
    ((__nv_bfloat162*)L)[i * 2 + 0] = __nv_bfloat162(
        __float2bfloat16(v.x - __bfloat162float(h0)), __float2bfloat16(v.y - __bfloat162float(h1)));
    ((__nv_bfloat162*)L)[i * 2 + 1] = __nv_bfloat162(
        __float2bfloat16(v.z - __bfloat162float(h2)), __float2bfloat16(v.w - __bfloat162float(h3)));
}

// ---------------- transpose fp32 [K,N] -> bf16 hi/lo [N,K] ------------------
__global__ __launch_bounds__(256)
void transpose_hilo(const float* __restrict__ W, bf16* __restrict__ Th, bf16* __restrict__ Tl,
                    int K, int N)
{
    __shared__ float t[32][33];
    const int nb = blockIdx.x * 32, kb = blockIdx.y * 32;
    const int tx = threadIdx.x & 31, ty = (threadIdx.x >> 5) * 4;
#pragma unroll
    for (int i = 0; i < 4; i++)
        t[ty + i][tx] = W[(size_t)(kb + ty + i) * N + nb + tx];
    __syncthreads();
#pragma unroll
    for (int i = 0; i < 4; i++) {
        const float v = t[tx][ty + i];
        const bf16 hv = __float2bfloat16(v);
        Th[(size_t)(nb + ty + i) * K + kb + tx] = hv;
        Tl[(size_t)(nb + ty + i) * K + kb + tx] = __float2bfloat16(v - __bfloat162float(hv));
    }
}

// ---------------- local (banded) attention: split-key, 256 threads ----------
// thread (qi, half): half 0 -> band slots [0,192); half 1 -> [192,384) + globals.
// Independent online-softmax states merged via smem scratch (reuses ks region).
#define LOC_SMEM ((384*64*2 + 32*64*2 + 384 + 32) * sizeof(float))

__global__ __launch_bounds__(256)
void local_attn(const float* __restrict__ q, const float* __restrict__ k,
                const float* __restrict__ v, const float* __restrict__ am,
                bf16* __restrict__ ctx_hi, bf16* __restrict__ ctx_lo)
{
    extern __shared__ float sm[];
    float* ks  = sm;
    float* vs  = ks + 384 * 64;
    float* gks = vs + 384 * 64;
    float* gvs = gks + 32 * 64;
    float* ams = gvs + 32 * 64;

    const int c = blockIdx.x, bh = blockIdx.y;
    const int b = bh / NHH, h = bh % NHH;
    const int tid = threadIdx.x;
    const int qi = tid & 127, half = tid >> 7;
    const float* kb = k + (size_t)bh * SS * DH;
    const float* vb = v + (size_t)bh * SS * DH;
    const int base = c * WW - WW;

    for (int i = tid; i < 384 * 64; i += 256) {
        const int j = i >> 6, d = i & 63;
        const int kp = base + j;
        const bool in = (kp >= 0 && kp < SS);
        ks[i] = in ? kb[(size_t)kp * DH + d] : 0.f;
        vs[i] = in ? vb[(size_t)kp * DH + d] : 0.f;
    }
    for (int i = tid; i < 32 * 64; i += 256) { gks[i] = kb[i]; gvs[i] = vb[i]; }
    for (int j = tid; j < 384; j += 256) {
        const int kp = base + j;
        ams[j] = (kp >= 0 && kp < SS) ? am[b * SS + kp] : 0.f;
    }
    if (tid < 32) ams[384 + tid] = am[b * SS + tid];
    __syncthreads();

    const int s = c * WW + qi;
    float qr[64];
    const float* qp = q + ((size_t)bh * SS + s) * DH;
#pragma unroll
    for (int d = 0; d < 64; d += 4) {
        float4 t = *(const float4*)&qp[d];
        qr[d] = t.x; qr[d + 1] = t.y; qr[d + 2] = t.z; qr[d + 3] = t.w;
    }

    float mval = -1e30f, l = 0.f;
    float acc[64];
#pragma unroll
    for (int d = 0; d < 64; d++) acc[d] = 0.f;

    const int j0 = half ? 192 : 0;
    const int j1 = half ? 384 : 192;
    for (int j = j0; j < j1; j++) {
        const int kp = base + j;
        const int dlt = kp - s;
        if (dlt < -WW || dlt > WW || kp < NGG || kp >= SS) continue;
        const float* kr = &ks[j * 64];
        float s0 = 0.f, s1 = 0.f, s2 = 0.f, s3 = 0.f;
#pragma unroll
        for (int d = 0; d < 64; d += 4) {
            s0 += qr[d]     * kr[d];
            s1 += qr[d + 1] * kr[d + 1];
            s2 += qr[d + 2] * kr[d + 2];
            s3 += qr[d + 3] * kr[d + 3];
        }
        const float sc = (s0 + s1) + (s2 + s3) + ams[j];
        const float mn = fmaxf(mval, sc);
        const float corr = __expf(mval - mn);
        const float p = __expf(sc - mn);
        l = l * corr + p;
        const float* vr = &vs[j * 64];
#pragma unroll
        for (int d = 0; d < 64; d++) acc[d] = acc[d] * corr + p * vr[d];
        mval = mn;
    }
    if (half) {
        for (int j = 0; j < 32; j++) {
            const float* kr = &gks[j * 64];
            float s0 = 0.f, s1 = 0.f, s2 = 0.f, s3 = 0.f;
#pragma unroll
            for (int d = 0; d < 64; d += 4) {
                s0 += qr[d]     * kr[d];
                s1 += qr[d + 1] * kr[d + 1];
                s2 += qr[d + 2] * kr[d + 2];
                s3 += qr[d + 3] * kr[d + 3];
            }
            const float sc = (s0 + s1) + (s2 + s3) + ams[384 + j];
            const float mn = fmaxf(mval, sc);
            const float corr = __expf(mval - mn);
            const float p = __expf(sc - mn);
            l = l * corr + p;
            const float* vr = &gvs[j * 64];
#pragma unroll
            for (int d = 0; d < 64; d++) acc[d] = acc[d] * corr + p * vr[d];
            mval = mn;
        }
    }

    __syncthreads();               // everyone done reading ks/vs -> reuse as scratch
    float* scratch = ks;           // 128 x 66 floats = 33 KB
    if (half) {
        float* sp = scratch + qi * 66;
        sp[0] = mval; sp[1] = l;
#pragma unroll
        for (int d = 0; d < 64; d++) sp[2 + d] = acc[d];
    }
    __syncthreads();
    if (!half && s >= NGG) {
        const float* sp = scratch + qi * 66;
        const float m1 = sp[0], l1 = sp[1];
        const float mh = fmaxf(mval, m1);
        const float c0 = __expf(mval - mh);
        const float c1 = __expf(m1 - mh);
        const float inv = 1.f / (l * c0 + l1 * c1);
        const size_t ob = ((size_t)(b * SS + s)) * DDIM + h * DH;
#pragma unroll
        for (int d = 0; d < 64; d++) {
            const float val = (acc[d] * c0 + sp[2 + d] * c1) * inv;
            const bf16 hv = __float2bfloat16(val);
            ctx_hi[ob + d] = hv;
            ctx_lo[ob + d] = __float2bfloat16(val - __bfloat162float(hv));
        }
    }
}

// ---------------- global-row attention --------------------------------------
__global__ __launch_bounds__(128)
void global_attn(const float* __restrict__ q, const float* __restrict__ k,
                 const float* __restrict__ v, const float* __restrict__ am,
                 bf16* __restrict__ ctx_hi, bf16* __restrict__ ctx_lo)
{
    __shared__ float lg[SS];
    __shared__ float qs[64];
    __shared__ float red[128];

    const int g = blockIdx.x, bh = blockIdx.y;
    const int b = bh / NHH, h = bh % NHH;
    const int tid = threadIdx.x;

    if (tid < 64) qs[tid] = q[((size_t)bh * SS + g) * DH + tid];
    __syncthreads();

    const float* kb = k + (size_t)bh * SS * DH;
    for (int s = tid; s < SS; s += 128) {
        const float4* kr = (const float4*)&kb[(size_t)s * DH];
        float s0 = 0.f, s1 = 0.f, s2 = 0.f, s3 = 0.f;
#pragma unroll
        for (int d4 = 0; d4 < 16; d4++) {
            const float4 kv = kr[d4];
            s0 += qs[d4 * 4 + 0] * kv.x;
            s1 += qs[d4 * 4 + 1] * kv.y;
            s2 += qs[d4 * 4 + 2] * kv.z;
            s3 += qs[d4 * 4 + 3] * kv.w;
        }
        lg[s] = (s0 + s1) + (s2 + s3) + am[b * SS + s];
    }
    __syncthreads();

    float mx = -1e30f;
    for (int s = tid; s < SS; s += 128) mx = fmaxf(mx, lg[s]);
    red[tid] = mx;
    __syncthreads();
    for (int st = 64; st > 0; st >>= 1) {
        if (tid < st) red[tid] = fmaxf(red[tid], red[tid + st]);
        __syncthreads();
    }
    mx = red[0];
    __syncthreads();

    float sum = 0.f;
    for (int s = tid; s < SS; s += 128) {
        const float e = __expf(lg[s] - mx);
        lg[s] = e;
        sum += e;
    }
    red[tid] = sum;
    __syncthreads();
    for (int st = 64; st > 0; st >>= 1) {
        if (tid < st) red[tid] += red[tid + st];
        __syncthreads();
    }
    const float inv = 1.f / red[0];
    __syncthreads();

    const float* vb = v + (size_t)bh * SS * DH;
    const int d = tid & 63, half = tid >> 6;
    float acc = 0.f;
    const int s0 = half * (SS / 2), s1 = s0 + SS / 2;
    for (int s = s0; s < s1; s++)
        acc += lg[s] * vb[(size_t)s * DH + d];
    red[tid] = acc;
    __syncthreads();
    if (tid < 64) {
        const float val = (red[tid] + red[tid + 64]) * inv;
        const size_t ob = ((size_t)(b * SS + g)) * DDIM + h * DH + d;
        const bf16 hv = __float2bfloat16(val);
        ctx_hi[ob] = hv;
        ctx_lo[ob] = __float2bfloat16(val - __bfloat162float(hv));
    }
}

// ---------------- layernorm (optional bf16 hi/lo side output) ---------------
__global__ __launch_bounds__(256)
void layernorm_k(const float* __restrict__ X, const float* __restrict__ gw,
                 const float* __restrict__ bw, float* __restrict__ Y,
                 bf16* __restrict__ Yh, bf16* __restrict__ Yl)
{
    __shared__ float xs[DDIM];
    __shared__ float red[256];
    const int row = blockIdx.x, tid = threadIdx.x;
    const float* xp = X + (size_t)row * DDIM;

    float sum = 0.f;
    for (int i = tid; i < DDIM; i += 256) { const float t = xp[i]; xs[i] = t; sum += t; }
    red[tid] = sum;
    __syncthreads();
    for (int st = 128; st > 0; st >>= 1) {
        if (tid < st) red[tid] += red[tid + st];
        __syncthreads();
    }
    const float mu = red[0] * (1.f / DDIM);
    __syncthreads();

    float vsum = 0.f;
    for (int i = tid; i < DDIM; i += 256) { const float d = xs[i] - mu; vsum += d * d; }
    red[tid] = vsum;
    __syncthreads();
    for (int st = 128; st > 0; st >>= 1) {
        if (tid < st) red[tid] += red[tid + st];
        __syncthreads();
    }
    const float rstd = rsqrtf(red[0] * (1.f / DDIM) + 1e-12f);
    for (int i = tid; i < DDIM; i += 256) {
        const float val = (xs[i] - mu) * rstd * gw[i] + bw[i];
        Y[(size_t)row * DDIM + i] = val;
        if (Yh) {
            const bf16 hv = __float2bfloat16(val);
            Yh[(size_t)row * DDIM + i] = hv;
            Yl[(size_t)row * DDIM + i] = __float2bfloat16(val - __bfloat162float(hv));
        }
    }
}

// ---------------- launch ----------------------------------------------------
extern "C" void kernel_launch(void* const* d_in, const int* in_sizes, int n_in,
                              void* d_out, int out_size)
{
    const float* h    = (const float*)d_in[0];
    const float* am   = (const float*)d_in[1];
    const float* Wq   = (const float*)d_in[2];
    const float* bq   = (const float*)d_in[3];
    const float* Wk   = (const float*)d_in[4];
    const float* bk   = (const float*)d_in[5];
    const float* Wv   = (const float*)d_in[6];
    const float* bv   = (const float*)d_in[7];
    const float* Wo   = (const float*)d_in[8];
    const float* bo   = (const float*)d_in[9];
    const float* ln1g = (const float*)d_in[10];
    const float* ln1b = (const float*)d_in[11];
    const float* Wi   = (const float*)d_in[12];
    const float* bi   = (const float*)d_in[13];
    const float* Wo2  = (const float*)d_in[14];
    const float* bo2  = (const float*)d_in[15];
    const float* ln2g = (const float*)d_in[16];
    const float* ln2b = (const float*)d_in[17];

    float *q, *k, *v, *x1, *attn, *x2;
    bf16 *h_hi, *h_lo, *ctx_hi, *ctx_lo, *at_hi, *at_lo, *in_hi, *in_lo;
    bf16 *wqt_hi, *wqt_lo, *wkt_hi, *wkt_lo, *wvt_hi, *wvt_lo, *wot_hi, *wot_lo;
    bf16 *wit_hi, *wit_lo, *wo2t_hi, *wo2t_lo;
    cudaGetSymbolAddress((void**)&q,    g_q);
    cudaGetSymbolAddress((void**)&k,    g_k);
    cudaGetSymbolAddress((void**)&v,    g_v);
    cudaGetSymbolAddress((void**)&x1,   g_x1);
    cudaGetSymbolAddress((void**)&attn, g_attn);
    cudaGetSymbolAddress((void**)&x2,   g_x2);
    cudaGetSymbolAddress((void**)&h_hi, g_h_hi);
    cudaGetSymbolAddress((void**)&h_lo, g_h_lo);
    cudaGetSymbolAddress((void**)&ctx_hi, g_ctx_hi);
    cudaGetSymbolAddress((void**)&ctx_lo, g_ctx_lo);
    cudaGetSymbolAddress((void**)&at_hi, g_at_hi);
    cudaGetSymbolAddress((void**)&at_lo, g_at_lo);
    cudaGetSymbolAddress((void**)&in_hi, g_in_hi);
    cudaGetSymbolAddress((void**)&in_lo, g_in_lo);
    cudaGetSymbolAddress((void**)&wqt_hi, g_wqt_hi);
    cudaGetSymbolAddress((void**)&wqt_lo, g_wqt_lo);
    cudaGetSymbolAddress((void**)&wkt_hi, g_wkt_hi);
    cudaGetSymbolAddress((void**)&wkt_lo, g_wkt_lo);
    cudaGetSymbolAddress((void**)&wvt_hi, g_wvt_hi);
    cudaGetSymbolAddress((void**)&wvt_lo, g_wvt_lo);
    cudaGetSymbolAddress((void**)&wot_hi, g_wot_hi);
    cudaGetSymbolAddress((void**)&wot_lo, g_wot_lo);
    cudaGetSymbolAddress((void**)&wit_hi, g_wit_hi);
    cudaGetSymbolAddress((void**)&wit_lo, g_wit_lo);
    cudaGetSymbolAddress((void**)&wo2t_hi, g_wo2t_hi);
    cudaGetSymbolAddress((void**)&wo2t_lo, g_wo2t_lo);

    cudaFuncSetAttribute(local_attn, cudaFuncAttributeMaxDynamicSharedMemorySize, (int)LOC_SMEM);
    cudaFuncSetAttribute(mma_gemm, cudaFuncAttributeMaxDynamicSharedMemorySize, GEMM_SMEM);

    // --- prepare bf16 hi/lo operands ---
    convert_hilo<<<(MM * DDIM / 4 + 255) / 256, 256>>>(h, h_hi, h_lo, MM * DDIM / 4);
    transpose_hilo<<<dim3(DDIM / 32, DDIM / 32), 256>>>(Wq,  wqt_hi,  wqt_lo,  DDIM, DDIM);
    transpose_hilo<<<dim3(DDIM / 32, DDIM / 32), 256>>>(Wk,  wkt_hi,  wkt_lo,  DDIM, DDIM);
    transpose_hilo<<<dim3(DDIM / 32, DDIM / 32), 256>>>(Wv,  wvt_hi,  wvt_lo,  DDIM, DDIM);
    transpose_hilo<<<dim3(DDIM / 32, DDIM / 32), 256>>>(Wo,  wot_hi,  wot_lo,  DDIM, DDIM);
    transpose_hilo<<<dim3(FF / 32,   DDIM / 32), 256>>>(Wi,  wit_hi,  wit_lo,  DDIM, FF);   // [3072][768]
    transpose_hilo<<<dim3(DDIM / 32, FF / 32),   256>>>(Wo2, wo2t_hi, wo2t_lo, FF, DDIM);   // [768][3072]

    const dim3 gD(DDIM / GB_N, MM / GB_M);   // (6, 64)
    const dim3 gF(FF / GB_N,   MM / GB_M);   // (24, 64)

    // --- QKV projections ---
    mma_gemm<<<gD, 256, GEMM_SMEM>>>(h_hi, h_lo, wqt_hi, wqt_lo, bq, nullptr, q, nullptr, nullptr,
                                     MM, DDIM, DDIM, EP_QKV, 0.125f);
    mma_gemm<<<gD, 256, GEMM_SMEM>>>(h_hi, h_lo, wkt_hi, wkt_lo, bk, nullptr, k, nullptr, nullptr,
                                     MM, DDIM, DDIM, EP_QKV, 1.f);
    mma_gemm<<<gD, 256, GEMM_SMEM>>>(h_hi, h_lo, wvt_hi, wvt_lo, bv, nullptr, v, nullptr, nullptr,
                                     MM, DDIM, DDIM, EP_QKV, 1.f);

    // --- attention (writes ctx directly as bf16 hi/lo) ---
    local_attn<<<dim3(CC, BB * NHH), 256, LOC_SMEM>>>(q, k, v, am, ctx_hi, ctx_lo);
    global_attn<<<dim3(NGG, BB * NHH), 128>>>(q, k, v, am, ctx_hi, ctx_lo);

    // --- output projection + residual, LN1 (LN emits bf16 hi/lo too) ---
    mma_gemm<<<gD, 256, GEMM_SMEM>>>(ctx_hi, ctx_lo, wot_hi, wot_lo, bo, h, x1, nullptr, nullptr,
                                     MM, DDIM, DDIM, EP_RES, 1.f);
    layernorm_k<<<MM, 256>>>(x1, ln1g, ln1b, attn, at_hi, at_lo);

    // --- FFN ---
    mma_gemm<<<gF, 256, GEMM_SMEM>>>(at_hi, at_lo, wit_hi, wit_lo, bi, nullptr, nullptr, in_hi, in_lo,
                                     MM, FF, DDIM, EP_GELU_BF, 1.f);
    mma_gemm<<<gD, 256, GEMM_SMEM>>>(in_hi, in_lo, wo2t_hi, wo2t_lo, bo2, attn, x2, nullptr, nullptr,
                                     MM, DDIM, FF, EP_RES, 1.f);
    layernorm_k<<<MM, 256>>>(x2, ln2g, ln2b, (float*)d_out, nullptr, nullptr);
}

// round 12
// speedup vs baseline: 2.1271x; 1.0282x over previous
#include <cuda_runtime.h>
#include <cuda_bf16.h>
#include <math.h>
#include <stdint.h>

// ---------------- problem constants ----------------
#define BB   2
#define SS   4096
#define DDIM 768
#define FF   3072
#define NHH  12
#define DH   64
#define WW   128
#define NGG  32
#define CC   (SS/WW)      // 32 chunks
#define MM   (BB*SS)      // 8192 rows

typedef __nv_bfloat16 bf16;

// ---------------- scratch (static device arrays; no allocs allowed) ----------
__device__ float g_q   [BB*NHH*SS*DH];
__device__ float g_k   [BB*NHH*SS*DH];
__device__ float g_v   [BB*NHH*SS*DH];
__device__ float g_x1  [MM*DDIM];
__device__ float g_attn[MM*DDIM];
__device__ float g_x2  [MM*DDIM];

__device__ bf16 g_h_hi [MM*DDIM];
__device__ bf16 g_h_lo [MM*DDIM];
__device__ bf16 g_ctx_hi[MM*DDIM];
__device__ bf16 g_ctx_lo[MM*DDIM];
__device__ bf16 g_at_hi[MM*DDIM];
__device__ bf16 g_at_lo[MM*DDIM];
__device__ bf16 g_in_hi[(size_t)MM*FF];
__device__ bf16 g_in_lo[(size_t)MM*FF];

__device__ bf16 g_wqkvt_hi[3*DDIM*DDIM], g_wqkvt_lo[3*DDIM*DDIM];  // [2304][768]
__device__ bf16 g_wot_hi[DDIM*DDIM], g_wot_lo[DDIM*DDIM];
__device__ bf16 g_wit_hi[DDIM*FF],   g_wit_lo[DDIM*FF];    // [3072][768]
__device__ bf16 g_wo2t_hi[DDIM*FF],  g_wo2t_lo[DDIM*FF];   // [768][3072]

// ================= helpers =================
__device__ __forceinline__ uint32_t smem_u32(const void* p) {
    uint32_t a;
    asm("{ .reg .u64 t; cvta.to.shared.u64 t, %1; cvt.u32.u64 %0, t; }" : "=r"(a) : "l"(p));
    return a;
}
__device__ __forceinline__ void cpa16(uint32_t s, const void* g) {
    asm volatile("cp.async.cg.shared.global [%0], [%1], 16;\n" :: "r"(s), "l"(g));
}
__device__ __forceinline__ void ldsm4(uint32_t& r0, uint32_t& r1, uint32_t& r2, uint32_t& r3,
                                      uint32_t addr) {
    asm volatile("ldmatrix.sync.aligned.m8n8.x4.shared.b16 {%0,%1,%2,%3}, [%4];"
                 : "=r"(r0), "=r"(r1), "=r"(r2), "=r"(r3) : "r"(addr));
}
__device__ __forceinline__ void mma_bf16(float* c, const uint32_t* a, const uint32_t* b) {
    asm volatile("mma.sync.aligned.m16n8k16.row.col.f32.bf16.bf16.f32 "
                 "{%0,%1,%2,%3}, {%4,%5,%6,%7}, {%8,%9}, {%0,%1,%2,%3};"
                 : "+f"(c[0]), "+f"(c[1]), "+f"(c[2]), "+f"(c[3])
                 : "r"(a[0]), "r"(a[1]), "r"(a[2]), "r"(a[3]), "r"(b[0]), "r"(b[1]));
}
__device__ __forceinline__ uint32_t sw_off(int row, int c) {
    return ((uint32_t)(row >> 1) * 128) +
           (uint32_t)(((((row & 1) * 4) + c) ^ ((row >> 1) & 7)) * 16);
}

// ================= bf16 split GEMM (templated tile) =========================
// C[M,N] = (Ahi+Alo)(Bhi+Blo)^T, 3-term split, fp32 accum.
// A: [M,K] bf16 hi/lo. B: [N,K] bf16 hi/lo (pre-transposed).
// GBM = MWARPS*MT*16 = 128; GBN = NWARPS*NT*8 (128 or 64).
// K-chunk 32, 3-stage cp.async, 2 CTAs/SM, conflict-free pair-packed swizzle.
#define EP_QKV     0
#define EP_RES     1
#define EP_GELU_BF 2
#define NSTG 3

template<int MWARPS, int NWARPS, int MT, int NT, int MODE>
__global__ __launch_bounds__(256, 2)
void mma_gemm(const bf16* __restrict__ Ahi, const bf16* __restrict__ Alo,
              const bf16* __restrict__ Bhi, const bf16* __restrict__ Blo,
              const float* __restrict__ biasQ, const float* __restrict__ biasK,
              const float* __restrict__ biasV, const float* __restrict__ R,
              float* __restrict__ C0, float* __restrict__ C1, float* __restrict__ C2,
              bf16* __restrict__ Chi, bf16* __restrict__ Clo,
              int M, int N, int K)
{
    constexpr int GBN   = NWARPS * NT * 8;
    constexpr int MAT_A = 128 * 64;          // bytes per A matrix per stage
    constexpr int MAT_B = GBN * 64;
    constexpr int STG   = 2 * MAT_A + 2 * MAT_B;
    static_assert(MWARPS * MT * 16 == 128, "GBM must be 128");
    static_assert(NT == 4, "B-fragment loader assumes NT==4");

    extern __shared__ char smem[];
    const uint32_t sdata = smem_u32(smem);
    const int tid = threadIdx.x;
    const int wid = tid >> 5, lane = tid & 31;
    const int warp_m = wid % MWARPS;
    const int warp_n = wid / MWARPS;
    const int m0 = blockIdx.y * 128, n0 = blockIdx.x * GBN;

    const int aRow   = lane & 15;
    const int aChunk = lane >> 4;
    const int bRow   = (lane & 7) + ((lane >> 4) << 3);
    const int bChunk = (lane >> 3) & 1;

    float acc[MT][NT][4];
#pragma unroll
    for (int i = 0; i < MT; i++)
#pragma unroll
        for (int j = 0; j < NT; j++)
#pragma unroll
            for (int t = 0; t < 4; t++) acc[i][j][t] = 0.f;

    auto load_stage = [&](int buf, int k0) {
        const int r  = tid >> 1;
        const int cg = (tid & 1) * 2;
        const uint32_t sb = sdata + buf * STG;
        const size_t ao = (size_t)(m0 + r) * K + k0;
#pragma unroll
        for (int cc = 0; cc < 2; cc++) {
            const int c = cg + cc;
            const uint32_t off = sw_off(r, c);
            cpa16(sb + off,         Ahi + ao + c * 8);
            cpa16(sb + MAT_A + off, Alo + ao + c * 8);
        }
        if (r < GBN) {
            const size_t bo = (size_t)(n0 + r) * K + k0;
#pragma unroll
            for (int cc = 0; cc < 2; cc++) {
                const int c = cg + cc;
                const uint32_t off = sw_off(r, c);
                cpa16(sb + 2 * MAT_A + off,         Bhi + bo + c * 8);
                cpa16(sb + 2 * MAT_A + MAT_B + off, Blo + bo + c * 8);
            }
        }
        asm volatile("cp.async.commit_group;" ::: "memory");
    };

    const int NK = K / 32;
    load_stage(0, 0);
    load_stage(1, 32);

    for (int j = 0; j < NK; j++) {
        if (j + NSTG - 1 < NK)
            load_stage((j + NSTG - 1) % NSTG, (j + NSTG - 1) * 32);
        const int rem = NK - 1 - j;
        if (rem >= 2)      asm volatile("cp.async.wait_group 2;" ::: "memory");
        else if (rem == 1) asm volatile("cp.async.wait_group 1;" ::: "memory");
        else               asm volatile("cp.async.wait_group 0;" ::: "memory");
        __syncthreads();

        const uint32_t sb  = sdata + (j % NSTG) * STG;
        const uint32_t sAh = sb;
        const uint32_t sAl = sb + MAT_A;
        const uint32_t sBh = sb + 2 * MAT_A;
        const uint32_t sBl = sb + 2 * MAT_A + MAT_B;

#pragma unroll
        for (int s = 0; s < 2; s++) {       // 2 x k16 steps within BK=32
            const int c0 = 2 * s;
            uint32_t bfh[4][2], bfl[4][2];
#pragma unroll
            for (int bt = 0; bt < 2; bt++) {
                const int nrow = warp_n * 32 + bt * 16 + bRow;
                const uint32_t off = sw_off(nrow, c0 + bChunk);
                ldsm4(bfh[2*bt][0], bfh[2*bt][1], bfh[2*bt+1][0], bfh[2*bt+1][1], sBh + off);
                ldsm4(bfl[2*bt][0], bfl[2*bt][1], bfl[2*bt+1][0], bfl[2*bt+1][1], sBl + off);
            }
#pragma unroll
            for (int mt = 0; mt < MT; mt++) {
                const int arow = warp_m * (MT * 16) + mt * 16 + aRow;
                const uint32_t off = sw_off(arow, c0 + aChunk);
                uint32_t ah[4], al[4];
                ldsm4(ah[0], ah[1], ah[2], ah[3], sAh + off);
                ldsm4(al[0], al[1], al[2], al[3], sAl + off);
#pragma unroll
                for (int nt = 0; nt < NT; nt++) {
                    mma_bf16(acc[mt][nt], ah, bfh[nt]);
                    mma_bf16(acc[mt][nt], al, bfh[nt]);
                    mma_bf16(acc[mt][nt], ah, bfl[nt]);
                }
            }
        }
        __syncthreads();
    }

    // ---------------- epilogue (from registers) ----------------
    const int rbase = lane >> 2;
    const int cbase = (lane & 3) * 2;

    // EP_QKV: CTA-uniform selection (GBN=128 divides 768)
    const float* bs = biasQ;
    float* Cq = C0;
    float qscale = 1.f;
    int nsub = 0;
    if (MODE == EP_QKV) {
        const int which = n0 / DDIM;
        bs = (which == 0) ? biasQ : (which == 1) ? biasK : biasV;
        Cq = (which == 0) ? C0 : (which == 1) ? C1 : C2;
        qscale = (which == 0) ? 0.125f : 1.f;
        nsub = which * DDIM;
    }

#pragma unroll
    for (int mt = 0; mt < MT; mt++) {
#pragma unroll
        for (int half = 0; half < 2; half++) {
            const int m = m0 + warp_m * (MT * 16) + mt * 16 + rbase + half * 8;
            const int bidx = m >> 12, srow = m & (SS - 1);
#pragma unroll
            for (int nt = 0; nt < NT; nt++) {
                const int n = n0 + warp_n * (NT * 8) + nt * 8 + cbase;
                const float v0r = acc[mt][nt][half * 2 + 0];
                const float v1r = acc[mt][nt][half * 2 + 1];
                if (MODE == EP_QKV) {
                    const int nrel = n - nsub;
                    const int hh = nrel >> 6, d0 = nrel & 63;
                    float2 vv;
                    vv.x = (v0r + bs[nrel])     * qscale;
                    vv.y = (v1r + bs[nrel + 1]) * qscale;
                    *(float2*)&Cq[(((size_t)(bidx * NHH + hh)) * SS + srow) * DH + d0] = vv;
                } else if (MODE == EP_RES) {
                    const size_t o = (size_t)m * N + n;
                    const float2 rv = *(const float2*)&R[o];
                    float2 vv;
                    vv.x = v0r + biasQ[n]     + rv.x;
                    vv.y = v1r + biasQ[n + 1] + rv.y;
                    *(float2*)&C0[o] = vv;
                } else { // EP_GELU_BF
                    float v0 = v0r + biasQ[n];
                    float v1 = v1r + biasQ[n + 1];
                    v0 = 0.5f * v0 * (1.f + erff(v0 * 0.70710678118654752f));
                    v1 = 0.5f * v1 * (1.f + erff(v1 * 0.70710678118654752f));
                    const bf16 h0 = __float2bfloat16(v0), h1 = __float2bfloat16(v1);
                    const bf16 l0 = __float2bfloat16(v0 - __bfloat162float(h0));
                    const bf16 l1 = __float2bfloat16(v1 - __bfloat162float(h1));
                    const size_t o = (size_t)m * N + n;
                    *(__nv_bfloat162*)&Chi[o] = __nv_bfloat162(h0, h1);
                    *(__nv_bfloat162*)&Clo[o] = __nv_bfloat162(l0, l1);
                }
            }
        }
    }
}

#define SMEM_128 (NSTG * (2*128*64 + 2*128*64))   // 98304
#define SMEM_64  (NSTG * (2*128*64 + 2*64*64))    // 73728

// ---------------- elementwise convert fp32 -> bf16 hi/lo --------------------
__global__ __launch_bounds__(256)
void convert_hilo(const float* __restrict__ X, bf16* __restrict__ H, bf16* __restrict__ L, int n4)
{
    const int i = blockIdx.x * 256 + threadIdx.x;
    if (i >= n4) return;
    const float4 v = ((const float4*)X)[i];
    bf16 h0 = __float2bfloat16(v.x), h1 = __float2bfloat16(v.y);
    bf16 h2 = __float2bfloat16(v.z), h3 = __float2bfloat16(v.w);
    ((__nv_bfloat162*)H)[i * 2 + 0] = __nv_bfloat162(h0, h1);
    ((__nv_bfloat162*)H)[i * 2 + 1] = __nv_bfloat162(h2, h3);
    ((__nv_bfloat162*)L)[i * 2 + 0] = __nv_bfloat162(
        __float2bfloat16(v.x - __bfloat162float(h0)), __float2bfloat16(v.y - __bfloat162float(h1)));
    ((__nv_bfloat162*)L)[i * 2 + 1] = __nv_bfloat162(
        __float2bfloat16(v.z - __bfloat162float(h2)), __float2bfloat16(v.w - __bfloat162float(h3)));
}

// ---------------- transpose fp32 [K,N] -> bf16 hi/lo [N,K] ------------------
__global__ __launch_bounds__(256)
void transpose_hilo(const float* __restrict__ W, bf16* __restrict__ Th, bf16* __restrict__ Tl,
                    int K, int N)
{
    __shared__ float t[32][33];
    const int nb = blockIdx.x * 32, kb = blockIdx.y * 32;
    const int tx = threadIdx.x & 31, ty = (threadIdx.x >> 5) * 4;
#pragma unroll
    for (int i = 0; i < 4; i++)
        t[ty + i][tx] = W[(size_t)(kb + ty + i) * N + nb + tx];
    __syncthreads();
#pragma unroll
    for (int i = 0; i < 4; i++) {
        const float v = t[tx][ty + i];
        const bf16 hv = __float2bfloat16(v);
        Th[(size_t)(nb + ty + i) * K + kb + tx] = hv;
        Tl[(size_t)(nb + ty + i) * K + kb + tx] = __float2bfloat16(v - __bfloat162float(hv));
    }
}

// ---------------- local (banded) attention: split-key, 256 threads ----------
#define LOC_SMEM ((384*64*2 + 32*64*2 + 384 + 32) * sizeof(float))

__global__ __launch_bounds__(256)
void local_attn(const float* __restrict__ q, const float* __restrict__ k,
                const float* __restrict__ v, const float* __restrict__ am,
                bf16* __restrict__ ctx_hi, bf16* __restrict__ ctx_lo)
{
    extern __shared__ float sm[];
    float* ks  = sm;
    float* vs  = ks + 384 * 64;
    float* gks = vs + 384 * 64;
    float* gvs = gks + 32 * 64;
    float* ams = gvs + 32 * 64;

    const int c = blockIdx.x, bh = blockIdx.y;
    const int b = bh / NHH, h = bh % NHH;
    const int tid = threadIdx.x;
    const int qi = tid & 127, half = tid >> 7;
    const float* kb = k + (size_t)bh * SS * DH;
    const float* vb = v + (size_t)bh * SS * DH;
    const int base = c * WW - WW;

    for (int i = tid; i < 384 * 64; i += 256) {
        const int j = i >> 6, d = i & 63;
        const int kp = base + j;
        const bool in = (kp >= 0 && kp < SS);
        ks[i] = in ? kb[(size_t)kp * DH + d] : 0.f;
        vs[i] = in ? vb[(size_t)kp * DH + d] : 0.f;
    }
    for (int i = tid; i < 32 * 64; i += 256) { gks[i] = kb[i]; gvs[i] = vb[i]; }
    for (int j = tid; j < 384; j += 256) {
        const int kp = base + j;
        ams[j] = (kp >= 0 && kp < SS) ? am[b * SS + kp] : 0.f;
    }
    if (tid < 32) ams[384 + tid] = am[b * SS + tid];
    __syncthreads();

    const int s = c * WW + qi;
    float qr[64];
    const float* qp = q + ((size_t)bh * SS + s) * DH;
#pragma unroll
    for (int d = 0; d < 64; d += 4) {
        float4 t = *(const float4*)&qp[d];
        qr[d] = t.x; qr[d + 1] = t.y; qr[d + 2] = t.z; qr[d + 3] = t.w;
    }

    float mval = -1e30f, l = 0.f;
    float acc[64];
#pragma unroll
    for (int d = 0; d < 64; d++) acc[d] = 0.f;

    const int j0 = half ? 192 : 0;
    const int j1 = half ? 384 : 192;
    for (int j = j0; j < j1; j++) {
        const int kp = base + j;
        const int dlt = kp - s;
        if (dlt < -WW || dlt > WW || kp < NGG || kp >= SS) continue;
        const float4* kr = (const float4*)&ks[j * 64];
        float s0 = 0.f, s1 = 0.f, s2 = 0.f, s3 = 0.f;
#pragma unroll
        for (int d4 = 0; d4 < 16; d4++) {
            const float4 kv = kr[d4];
            s0 += qr[d4*4+0] * kv.x;
            s1 += qr[d4*4+1] * kv.y;
            s2 += qr[d4*4+2] * kv.z;
            s3 += qr[d4*4+3] * kv.w;
        }
        const float sc = (s0 + s1) + (s2 + s3) + ams[j];
        const float mn = fmaxf(mval, sc);
        const float corr = __expf(mval - mn);
        const float p = __expf(sc - mn);
        l = l * corr + p;
        const float4* vr = (const float4*)&vs[j * 64];
#pragma unroll
        for (int d4 = 0; d4 < 16; d4++) {
            const float4 vv = vr[d4];
            acc[d4*4+0] = acc[d4*4+0] * corr + p * vv.x;
            acc[d4*4+1] = acc[d4*4+1] * corr + p * vv.y;
            acc[d4*4+2] = acc[d4*4+2] * corr + p * vv.z;
            acc[d4*4+3] = acc[d4*4+3] * corr + p * vv.w;
        }
        mval = mn;
    }
    if (half) {
        for (int j = 0; j < 32; j++) {
            const float4* kr = (const float4*)&gks[j * 64];
            float s0 = 0.f, s1 = 0.f, s2 = 0.f, s3 = 0.f;
#pragma unroll
            for (int d4 = 0; d4 < 16; d4++) {
                const float4 kv = kr[d4];
                s0 += qr[d4*4+0] * kv.x;
                s1 += qr[d4*4+1] * kv.y;
                s2 += qr[d4*4+2] * kv.z;
                s3 += qr[d4*4+3] * kv.w;
            }
            const float sc = (s0 + s1) + (s2 + s3) + ams[384 + j];
            const float mn = fmaxf(mval, sc);
            const float corr = __expf(mval - mn);
            const float p = __expf(sc - mn);
            l = l * corr + p;
            const float4* vr = (const float4*)&gvs[j * 64];
#pragma unroll
            for (int d4 = 0; d4 < 16; d4++) {
                const float4 vv = vr[d4];
                acc[d4*4+0] = acc[d4*4+0] * corr + p * vv.x;
                acc[d4*4+1] = acc[d4*4+1] * corr + p * vv.y;
                acc[d4*4+2] = acc[d4*4+2] * corr + p * vv.z;
                acc[d4*4+3] = acc[d4*4+3] * corr + p * vv.w;
            }
            mval = mn;
        }
    }

    __syncthreads();               // ks/vs dead -> reuse as scratch
    float* scratch = ks;           // 128 x 66 floats
    if (half) {
        float* sp = scratch + qi * 66;
        sp[0] = mval; sp[1] = l;
#pragma unroll
        for (int d = 0; d < 64; d++) sp[2 + d] = acc[d];
    }
    __syncthreads();
    if (!half && s >= NGG) {
        const float* sp = scratch + qi * 66;
        const float m1 = sp[0], l1 = sp[1];
        const float mh = fmaxf(mval, m1);
        const float c0 = __expf(mval - mh);
        const float c1 = __expf(m1 - mh);
        const float inv = 1.f / (l * c0 + l1 * c1);
        const size_t ob = ((size_t)(b * SS + s)) * DDIM + h * DH;
#pragma unroll
        for (int d = 0; d < 64; d++) {
            const float val = (acc[d] * c0 + sp[2 + d] * c1) * inv;
            const bf16 hv = __float2bfloat16(val);
            ctx_hi[ob + d] = hv;
            ctx_lo[ob + d] = __float2bfloat16(val - __bfloat162float(hv));
        }
    }
}

// ---------------- global-row attention --------------------------------------
__global__ __launch_bounds__(128)
void global_attn(const float* __restrict__ q, const float* __restrict__ k,
                 const float* __restrict__ v, const float* __restrict__ am,
                 bf16* __restrict__ ctx_hi, bf16* __restrict__ ctx_lo)
{
    __shared__ float lg[SS];
    __shared__ float qs[64];
    __shared__ float red[128];

    const int g = blockIdx.x, bh = blockIdx.y;
    const int b = bh / NHH, h = bh % NHH;
    const int tid = threadIdx.x;

    if (tid < 64) qs[tid] = q[((size_t)bh * SS + g) * DH + tid];
    __syncthreads();

    const float* kb = k + (size_t)bh * SS * DH;
    for (int s = tid; s < SS; s += 128) {
        const float4* kr = (const float4*)&kb[(size_t)s * DH];
        float s0 = 0.f, s1 = 0.f, s2 = 0.f, s3 = 0.f;
#pragma unroll
        for (int d4 = 0; d4 < 16; d4++) {
            const float4 kv = kr[d4];
            s0 += qs[d4 * 4 + 0] * kv.x;
            s1 += qs[d4 * 4 + 1] * kv.y;
            s2 += qs[d4 * 4 + 2] * kv.z;
            s3 += qs[d4 * 4 + 3] * kv.w;
        }
        lg[s] = (s0 + s1) + (s2 + s3) + am[b * SS + s];
    }
    __syncthreads();

    float mx = -1e30f;
    for (int s = tid; s < SS; s += 128) mx = fmaxf(mx, lg[s]);
    red[tid] = mx;
    __syncthreads();
    for (int st = 64; st > 0; st >>= 1) {
        if (tid < st) red[tid] = fmaxf(red[tid], red[tid + st]);
        __syncthreads();
    }
    mx = red[0];
    __syncthreads();

    float sum = 0.f;
    for (int s = tid; s < SS; s += 128) {
        const float e = __expf(lg[s] - mx);
        lg[s] = e;
        sum += e;
    }
    red[tid] = sum;
    __syncthreads();
    for (int st = 64; st > 0; st >>= 1) {
        if (tid < st) red[tid] += red[tid + st];
        __syncthreads();
    }
    const float inv = 1.f / red[0];
    __syncthreads();

    const float* vb = v + (size_t)bh * SS * DH;
    const int d = tid & 63, half = tid >> 6;
    float acc = 0.f;
    const int s0 = half * (SS / 2), s1 = s0 + SS / 2;
    for (int s = s0; s < s1; s++)
        acc += lg[s] * vb[(size_t)s * DH + d];
    red[tid] = acc;
    __syncthreads();
    if (tid < 64) {
        const float val = (red[tid] + red[tid + 64]) * inv;
        const size_t ob = ((size_t)(b * SS + g)) * DDIM + h * DH + d;
        const bf16 hv = __float2bfloat16(val);
        ctx_hi[ob] = hv;
        ctx_lo[ob] = __float2bfloat16(val - __bfloat162float(hv));
    }
}

// ---------------- layernorm (optional bf16 hi/lo side output) ---------------
__global__ __launch_bounds__(256)
void layernorm_k(const float* __restrict__ X, const float* __restrict__ gw,
                 const float* __restrict__ bw, float* __restrict__ Y,
                 bf16* __restrict__ Yh, bf16* __restrict__ Yl)
{
    __shared__ float xs[DDIM];
    __shared__ float red[256];
    const int row = blockIdx.x, tid = threadIdx.x;
    const float* xp = X + (size_t)row * DDIM;

    float sum = 0.f;
    for (int i = tid; i < DDIM; i += 256) { const float t = xp[i]; xs[i] = t; sum += t; }
    red[tid] = sum;
    __syncthreads();
    for (int st = 128; st > 0; st >>= 1) {
        if (tid < st) red[tid] += red[tid + st];
        __syncthreads();
    }
    const float mu = red[0] * (1.f / DDIM);
    __syncthreads();

    float vsum = 0.f;
    for (int i = tid; i < DDIM; i += 256) { const float d = xs[i] - mu; vsum += d * d; }
    red[tid] = vsum;
    __syncthreads();
    for (int st = 128; st > 0; st >>= 1) {
        if (tid < st) red[tid] += red[tid + st];
        __syncthreads();
    }
    const float rstd = rsqrtf(red[0] * (1.f / DDIM) + 1e-12f);
    for (int i = tid; i < DDIM; i += 256) {
        const float val = (xs[i] - mu) * rstd * gw[i] + bw[i];
        Y[(size_t)row * DDIM + i] = val;
        if (Yh) {
            const bf16 hv = __float2bfloat16(val);
            Yh[(size_t)row * DDIM + i] = hv;
            Yl[(size_t)row * DDIM + i] = __float2bfloat16(val - __bfloat162float(hv));
        }
    }
}

// ---------------- launch ----------------------------------------------------
extern "C" void kernel_launch(void* const* d_in, const int* in_sizes, int n_in,
                              void* d_out, int out_size)
{
    const float* h    = (const float*)d_in[0];
    const float* am   = (const float*)d_in[1];
    const float* Wq   = (const float*)d_in[2];
    const float* bq   = (const float*)d_in[3];
    const float* Wk   = (const float*)d_in[4];
    const float* bk   = (const float*)d_in[5];
    const float* Wv   = (const float*)d_in[6];
    const float* bv   = (const float*)d_in[7];
    const float* Wo   = (const float*)d_in[8];
    const float* bo   = (const float*)d_in[9];
    const float* ln1g = (const float*)d_in[10];
    const float* ln1b = (const float*)d_in[11];
    const float* Wi   = (const float*)d_in[12];
    const float* bi   = (const float*)d_in[13];
    const float* Wo2  = (const float*)d_in[14];
    const float* bo2  = (const float*)d_in[15];
    const float* ln2g = (const float*)d_in[16];
    const float* ln2b = (const float*)d_in[17];

    float *q, *k, *v, *x1, *attn, *x2;
    bf16 *h_hi, *h_lo, *ctx_hi, *ctx_lo, *at_hi, *at_lo, *in_hi, *in_lo;
    bf16 *wqkvt_hi, *wqkvt_lo, *wot_hi, *wot_lo, *wit_hi, *wit_lo, *wo2t_hi, *wo2t_lo;
    cudaGetSymbolAddress((void**)&q,    g_q);
    cudaGetSymbolAddress((void**)&k,    g_k);
    cudaGetSymbolAddress((void**)&v,    g_v);
    cudaGetSymbolAddress((void**)&x1,   g_x1);
    cudaGetSymbolAddress((void**)&attn, g_attn);
    cudaGetSymbolAddress((void**)&x2,   g_x2);
    cudaGetSymbolAddress((void**)&h_hi, g_h_hi);
    cudaGetSymbolAddress((void**)&h_lo, g_h_lo);
    cudaGetSymbolAddress((void**)&ctx_hi, g_ctx_hi);
    cudaGetSymbolAddress((void**)&ctx_lo, g_ctx_lo);
    cudaGetSymbolAddress((void**)&at_hi, g_at_hi);
    cudaGetSymbolAddress((void**)&at_lo, g_at_lo);
    cudaGetSymbolAddress((void**)&in_hi, g_in_hi);
    cudaGetSymbolAddress((void**)&in_lo, g_in_lo);
    cudaGetSymbolAddress((void**)&wqkvt_hi, g_wqkvt_hi);
    cudaGetSymbolAddress((void**)&wqkvt_lo, g_wqkvt_lo);
    cudaGetSymbolAddress((void**)&wot_hi, g_wot_hi);
    cudaGetSymbolAddress((void**)&wot_lo, g_wot_lo);
    cudaGetSymbolAddress((void**)&wit_hi, g_wit_hi);
    cudaGetSymbolAddress((void**)&wit_lo, g_wit_lo);
    cudaGetSymbolAddress((void**)&wo2t_hi, g_wo2t_hi);
    cudaGetSymbolAddress((void**)&wo2t_lo, g_wo2t_lo);

    cudaFuncSetAttribute(local_attn, cudaFuncAttributeMaxDynamicSharedMemorySize, (int)LOC_SMEM);
    cudaFuncSetAttribute(mma_gemm<2,4,4,4,EP_QKV>,     cudaFuncAttributeMaxDynamicSharedMemorySize, SMEM_128);
    cudaFuncSetAttribute(mma_gemm<2,4,4,4,EP_GELU_BF>, cudaFuncAttributeMaxDynamicSharedMemorySize, SMEM_128);
    cudaFuncSetAttribute(mma_gemm<4,2,2,4,EP_RES>,     cudaFuncAttributeMaxDynamicSharedMemorySize, SMEM_64);

    // --- prepare bf16 hi/lo operands ---
    convert_hilo<<<(MM * DDIM / 4 + 255) / 256, 256>>>(h, h_hi, h_lo, MM * DDIM / 4);
    transpose_hilo<<<dim3(DDIM / 32, DDIM / 32), 256>>>(Wq, wqkvt_hi,                wqkvt_lo,                DDIM, DDIM);
    transpose_hilo<<<dim3(DDIM / 32, DDIM / 32), 256>>>(Wk, wqkvt_hi + DDIM * DDIM,  wqkvt_lo + DDIM * DDIM,  DDIM, DDIM);
    transpose_hilo<<<dim3(DDIM / 32, DDIM / 32), 256>>>(Wv, wqkvt_hi + 2*DDIM*DDIM,  wqkvt_lo + 2*DDIM*DDIM,  DDIM, DDIM);
    transpose_hilo<<<dim3(DDIM / 32, DDIM / 32), 256>>>(Wo, wot_hi, wot_lo, DDIM, DDIM);
    transpose_hilo<<<dim3(FF / 32,   DDIM / 32), 256>>>(Wi,  wit_hi,  wit_lo,  DDIM, FF);
    transpose_hilo<<<dim3(DDIM / 32, FF / 32),   256>>>(Wo2, wo2t_hi, wo2t_lo, FF, DDIM);

    // --- merged QKV projection (N = 2304) ---
    mma_gemm<2,4,4,4,EP_QKV><<<dim3(3 * DDIM / 128, MM / 128), 256, SMEM_128>>>(
        h_hi, h_lo, wqkvt_hi, wqkvt_lo, bq, bk, bv, nullptr,
        q, k, v, nullptr, nullptr, MM, 3 * DDIM, DDIM);

    // --- attention ---
    local_attn<<<dim3(CC, BB * NHH), 256, LOC_SMEM>>>(q, k, v, am, ctx_hi, ctx_lo);
    global_attn<<<dim3(NGG, BB * NHH), 128>>>(q, k, v, am, ctx_hi, ctx_lo);

    // --- output projection + residual (128x64 tiles), LN1 ---
    mma_gemm<4,2,2,4,EP_RES><<<dim3(DDIM / 64, MM / 128), 256, SMEM_64>>>(
        ctx_hi, ctx_lo, wot_hi, wot_lo, bo, nullptr, nullptr, h,
        x1, nullptr, nullptr, nullptr, nullptr, MM, DDIM, DDIM);
    layernorm_k<<<MM, 256>>>(x1, ln1g, ln1b, attn, at_hi, at_lo);

    // --- FFN ---
    mma_gemm<2,4,4,4,EP_GELU_BF><<<dim3(FF / 128, MM / 128), 256, SMEM_128>>>(
        at_hi, at_lo, wit_hi, wit_lo, bi, nullptr, nullptr, nullptr,
        nullptr, nullptr, nullptr, in_hi, in_lo, MM, FF, DDIM);
    mma_gemm<4,2,2,4,EP_RES><<<dim3(DDIM / 64, MM / 128), 256, SMEM_64>>>(
        in_hi, in_lo, wo2t_hi, wo2t_lo, bo2, nullptr, nullptr, attn,
        x2, nullptr, nullptr, nullptr, nullptr, MM, DDIM, FF);
    layernorm_k<<<MM, 256>>>(x2, ln2g, ln2b, (float*)d_out, nullptr, nullptr);
}

// round 13
// speedup vs baseline: 3.4832x; 1.6376x over previous
#include <cuda_runtime.h>
#include <cuda_fp16.h>
#include <math.h>
#include <stdint.h>

// ---------------- problem constants ----------------
#define BB   2
#define SS   4096
#define DDIM 768
#define FF   3072
#define NHH  12
#define DH   64
#define WW   128
#define NGG  32
#define CC   (SS/WW)
#define MM   (BB*SS)

// ---------------- scratch ----------------
__device__ float g_q   [BB*NHH*SS*DH];
__device__ float g_k   [BB*NHH*SS*DH];
__device__ float g_v   [BB*NHH*SS*DH];
__device__ float g_x1  [MM*DDIM];
__device__ float g_attn[MM*DDIM];
__device__ float g_x2  [MM*DDIM];

__device__ __half g_h16  [MM*DDIM];
__device__ __half g_ctx16[MM*DDIM];
__device__ __half g_at16 [MM*DDIM];
__device__ __half g_in16 [(size_t)MM*FF];

__device__ __half g_wqkvt[3*DDIM*DDIM];   // [2304][768]
__device__ __half g_wot  [DDIM*DDIM];
__device__ __half g_wit  [DDIM*FF];       // [3072][768]
__device__ __half g_wo2t [DDIM*FF];       // [768][3072]

// ================= helpers =================
__device__ __forceinline__ uint32_t smem_u32(const void* p) {
    uint32_t a;
    asm("{ .reg .u64 t; cvta.to.shared.u64 t, %1; cvt.u32.u64 %0, t; }" : "=r"(a) : "l"(p));
    return a;
}
__device__ __forceinline__ void cpa16(uint32_t s, const void* g) {
    asm volatile("cp.async.cg.shared.global [%0], [%1], 16;\n" :: "r"(s), "l"(g));
}
__device__ __forceinline__ void ldsm4(uint32_t& r0, uint32_t& r1, uint32_t& r2, uint32_t& r3,
                                      uint32_t addr) {
    asm volatile("ldmatrix.sync.aligned.m8n8.x4.shared.b16 {%0,%1,%2,%3}, [%4];"
                 : "=r"(r0), "=r"(r1), "=r"(r2), "=r"(r3) : "r"(addr));
}
__device__ __forceinline__ void mma_f16(float* c, const uint32_t* a, const uint32_t* b) {
    asm volatile("mma.sync.aligned.m16n8k16.row.col.f32.f16.f16.f32 "
                 "{%0,%1,%2,%3}, {%4,%5,%6,%7}, {%8,%9}, {%0,%1,%2,%3};"
                 : "+f"(c[0]), "+f"(c[1]), "+f"(c[2]), "+f"(c[3])
                 : "r"(a[0]), "r"(a[1]), "r"(a[2]), "r"(a[3]), "r"(b[0]), "r"(b[1]));
}
// SW128 swizzle for 128B rows (K64 fp16): off(r, c16) = r*128 + ((c16 ^ (r&7))*16)
__device__ __forceinline__ uint32_t swz(int row, int c16) {
    return (uint32_t)row * 128 + (uint32_t)(((c16 ^ (row & 7)) & 7) * 16);
}

// ================= fp16 GEMM: C[M,N] = A[M,K] @ B[N,K]^T ====================
// Tile 128x128, K-chunk 64, 3-stage cp.async, ONE sync per chunk, 2 CTAs/SM.
#define EP_QKV     0
#define EP_RES     1
#define EP_GELU    2
#define NSTG 3
#define MAT_B16 (128*64*2)          // 16 KB per matrix per stage
#define STG16   (2*MAT_B16)         // 32 KB
#define SMEM16  (NSTG*STG16)        // 96 KB

template<int MODE>
__global__ __launch_bounds__(256, 2)
void gemm_f16(const __half* __restrict__ A, const __half* __restrict__ B,
              const float* __restrict__ biasQ, const float* __restrict__ biasK,
              const float* __restrict__ biasV, const float* __restrict__ R,
              float* __restrict__ C0, float* __restrict__ C1, float* __restrict__ C2,
              __half* __restrict__ Ch, int M, int N, int K)
{
    extern __shared__ char smem[];
    const uint32_t sdata = smem_u32(smem);
    const int tid = threadIdx.x;
    const int wid = tid >> 5, lane = tid & 31;
    const int warp_m = wid & 1;          // 2 warps along M (64 rows)
    const int warp_n = wid >> 1;         // 4 warps along N (32 cols)
    const int m0 = blockIdx.y * 128, n0 = blockIdx.x * 128;

    const int aRow   = lane & 15;
    const int aChunk = lane >> 4;
    const int bRow   = (lane & 7) + ((lane >> 4) << 3);
    const int bChunk = (lane >> 3) & 1;

    float acc[4][4][4];
#pragma unroll
    for (int i = 0; i < 4; i++)
#pragma unroll
        for (int j = 0; j < 4; j++)
#pragma unroll
            for (int t = 0; t < 4; t++) acc[i][j][t] = 0.f;

    const int r  = tid >> 1;             // loader row 0..127
    const int cg = (tid & 1) * 4;        // col16 group 0 or 4

    auto load_stage = [&](int buf, int k0) {
        const uint32_t sb = sdata + buf * STG16;
        const size_t ao = (size_t)(m0 + r) * K + k0;
        const size_t bo = (size_t)(n0 + r) * K + k0;
#pragma unroll
        for (int cc = 0; cc < 4; cc++) {
            const int c = cg + cc;
            const uint32_t off = swz(r, c);
            cpa16(sb + off,           A + ao + c * 8);
            cpa16(sb + MAT_B16 + off, B + bo + c * 8);
        }
        asm volatile("cp.async.commit_group;" ::: "memory");
    };

    const int NK = K / 64;
    load_stage(0, 0);
    load_stage(1, 64);

    for (int j = 0; j < NK; j++) {
        if (j == NK - 1) asm volatile("cp.async.wait_group 0;" ::: "memory");
        else             asm volatile("cp.async.wait_group 1;" ::: "memory");
        __syncthreads();

        const uint32_t sb = sdata + (j % NSTG) * STG16;
        const uint32_t sA = sb, sB = sb + MAT_B16;

#pragma unroll
        for (int s = 0; s < 4; s++) {         // 4 k16 steps in K64
            const int c0 = 2 * s;
            uint32_t bf[4][2];
#pragma unroll
            for (int bt = 0; bt < 2; bt++) {
                const int nrow = warp_n * 32 + bt * 16 + bRow;
                ldsm4(bf[2*bt][0], bf[2*bt][1], bf[2*bt+1][0], bf[2*bt+1][1],
                      sB + swz(nrow, c0 + bChunk));
            }
#pragma unroll
            for (int mt = 0; mt < 4; mt++) {
                const int arow = warp_m * 64 + mt * 16 + aRow;
                uint32_t ah[4];
                ldsm4(ah[0], ah[1], ah[2], ah[3], sA + swz(arow, c0 + aChunk));
#pragma unroll
                for (int nt = 0; nt < 4; nt++)
                    mma_f16(acc[mt][nt], ah, bf[nt]);
            }
        }
        if (j + 2 < NK) load_stage((j + 2) % NSTG, (j + 2) * 64);
    }

    // ---------------- epilogue ----------------
    const int rbase = lane >> 2;
    const int cbase = (lane & 3) * 2;

    const float* bs = biasQ;
    float* Cq = C0;
    float qscale = 1.f;
    int nsub = 0;
    if (MODE == EP_QKV) {
        const int which = n0 / DDIM;
        bs = (which == 0) ? biasQ : (which == 1) ? biasK : biasV;
        Cq = (which == 0) ? C0 : (which == 1) ? C1 : C2;
        qscale = (which == 0) ? 0.125f : 1.f;
        nsub = which * DDIM;
    }

#pragma unroll
    for (int mt = 0; mt < 4; mt++) {
#pragma unroll
        for (int half_ = 0; half_ < 2; half_++) {
            const int m = m0 + warp_m * 64 + mt * 16 + rbase + half_ * 8;
            const int bidx = m >> 12, srow = m & (SS - 1);
#pragma unroll
            for (int nt = 0; nt < 4; nt++) {
                const int n = n0 + warp_n * 32 + nt * 8 + cbase;
                const float v0r = acc[mt][nt][half_ * 2 + 0];
                const float v1r = acc[mt][nt][half_ * 2 + 1];
                if (MODE == EP_QKV) {
                    const int nrel = n - nsub;
                    const int hh = nrel >> 6, d0 = nrel & 63;
                    float2 vv;
                    vv.x = (v0r + bs[nrel])     * qscale;
                    vv.y = (v1r + bs[nrel + 1]) * qscale;
                    *(float2*)&Cq[(((size_t)(bidx * NHH + hh)) * SS + srow) * DH + d0] = vv;
                } else if (MODE == EP_RES) {
                    const size_t o = (size_t)m * N + n;
                    const float2 rv = *(const float2*)&R[o];
                    float2 vv;
                    vv.x = v0r + biasQ[n]     + rv.x;
                    vv.y = v1r + biasQ[n + 1] + rv.y;
                    *(float2*)&C0[o] = vv;
                } else { // EP_GELU -> fp16
                    float v0 = v0r + biasQ[n];
                    float v1 = v1r + biasQ[n + 1];
                    v0 = 0.5f * v0 * (1.f + erff(v0 * 0.70710678118654752f));
                    v1 = 0.5f * v1 * (1.f + erff(v1 * 0.70710678118654752f));
                    const size_t o = (size_t)m * N + n;
                    *(__half2*)&Ch[o] = __floats2half2_rn(v0, v1);
                }
            }
        }
    }
}

// ---------------- convert fp32 -> fp16 --------------------------------------
__global__ __launch_bounds__(256)
void convert_f16(const float* __restrict__ X, __half* __restrict__ H, int n4)
{
    const int i = blockIdx.x * 256 + threadIdx.x;
    if (i >= n4) return;
    const float4 v = ((const float4*)X)[i];
    ((__half2*)H)[i * 2 + 0] = __floats2half2_rn(v.x, v.y);
    ((__half2*)H)[i * 2 + 1] = __floats2half2_rn(v.z, v.w);
}

// ---------------- transpose fp32 [K,N] -> fp16 [N,K] ------------------------
__global__ __launch_bounds__(256)
void transpose_f16(const float* __restrict__ W, __half* __restrict__ T, int K, int N)
{
    __shared__ float t[32][33];
    const int nb = blockIdx.x * 32, kb = blockIdx.y * 32;
    const int tx = threadIdx.x & 31, ty = (threadIdx.x >> 5) * 4;
#pragma unroll
    for (int i = 0; i < 4; i++)
        t[ty + i][tx] = W[(size_t)(kb + ty + i) * N + nb + tx];
    __syncthreads();
#pragma unroll
    for (int i = 0; i < 4; i++)
        T[(size_t)(nb + ty + i) * K + kb + tx] = __float2half(t[tx][ty + i]);
}

// ---------------- local (banded) attention: split-key, 256 threads ----------
#define LOC_SMEM ((384*64*2 + 32*64*2 + 384 + 32) * sizeof(float))

__global__ __launch_bounds__(256)
void local_attn(const float* __restrict__ q, const float* __restrict__ k,
                const float* __restrict__ v, const float* __restrict__ am,
                __half* __restrict__ ctx16)
{
    extern __shared__ float sm[];
    float* ks  = sm;
    float* vs  = ks + 384 * 64;
    float* gks = vs + 384 * 64;
    float* gvs = gks + 32 * 64;
    float* ams = gvs + 32 * 64;

    const int c = blockIdx.x, bh = blockIdx.y;
    const int b = bh / NHH, h = bh % NHH;
    const int tid = threadIdx.x;
    const int qi = tid & 127, half_ = tid >> 7;
    const float* kb = k + (size_t)bh * SS * DH;
    const float* vb = v + (size_t)bh * SS * DH;
    const int base = c * WW - WW;

    for (int i = tid; i < 384 * 64; i += 256) {
        const int j = i >> 6, d = i & 63;
        const int kp = base + j;
        const bool in = (kp >= 0 && kp < SS);
        ks[i] = in ? kb[(size_t)kp * DH + d] : 0.f;
        vs[i] = in ? vb[(size_t)kp * DH + d] : 0.f;
    }
    for (int i = tid; i < 32 * 64; i += 256) { gks[i] = kb[i]; gvs[i] = vb[i]; }
    for (int j = tid; j < 384; j += 256) {
        const int kp = base + j;
        ams[j] = (kp >= 0 && kp < SS) ? am[b * SS + kp] : 0.f;
    }
    if (tid < 32) ams[384 + tid] = am[b * SS + tid];
    __syncthreads();

    const int s = c * WW + qi;
    float qr[64];
    const float* qp = q + ((size_t)bh * SS + s) * DH;
#pragma unroll
    for (int d = 0; d < 64; d += 4) {
        float4 t = *(const float4*)&qp[d];
        qr[d] = t.x; qr[d + 1] = t.y; qr[d + 2] = t.z; qr[d + 3] = t.w;
    }

    float mval = -1e30f, l = 0.f;
    float acc[64];
#pragma unroll
    for (int d = 0; d < 64; d++) acc[d] = 0.f;

    const int j0 = half_ ? 192 : 0;
    const int j1 = half_ ? 384 : 192;
    for (int j = j0; j < j1; j++) {
        const int kp = base + j;
        const int dlt = kp - s;
        if (dlt < -WW || dlt > WW || kp < NGG || kp >= SS) continue;
        const float4* kr = (const float4*)&ks[j * 64];
        float s0 = 0.f, s1 = 0.f, s2 = 0.f, s3 = 0.f;
#pragma unroll
        for (int d4 = 0; d4 < 16; d4++) {
            const float4 kv = kr[d4];
            s0 += qr[d4*4+0] * kv.x;
            s1 += qr[d4*4+1] * kv.y;
            s2 += qr[d4*4+2] * kv.z;
            s3 += qr[d4*4+3] * kv.w;
        }
        const float sc = (s0 + s1) + (s2 + s3) + ams[j];
        const float mn = fmaxf(mval, sc);
        const float corr = __expf(mval - mn);
        const float p = __expf(sc - mn);
        l = l * corr + p;
        const float4* vr = (const float4*)&vs[j * 64];
#pragma unroll
        for (int d4 = 0; d4 < 16; d4++) {
            const float4 vv = vr[d4];
            acc[d4*4+0] = acc[d4*4+0] * corr + p * vv.x;
            acc[d4*4+1] = acc[d4*4+1] * corr + p * vv.y;
            acc[d4*4+2] = acc[d4*4+2] * corr + p * vv.z;
            acc[d4*4+3] = acc[d4*4+3] * corr + p * vv.w;
        }
        mval = mn;
    }
    if (half_) {
        for (int j = 0; j < 32; j++) {
            const float4* kr = (const float4*)&gks[j * 64];
            float s0 = 0.f, s1 = 0.f, s2 = 0.f, s3 = 0.f;
#pragma unroll
            for (int d4 = 0; d4 < 16; d4++) {
                const float4 kv = kr[d4];
                s0 += qr[d4*4+0] * kv.x;
                s1 += qr[d4*4+1] * kv.y;
                s2 += qr[d4*4+2] * kv.z;
                s3 += qr[d4*4+3] * kv.w;
            }
            const float sc = (s0 + s1) + (s2 + s3) + ams[384 + j];
            const float mn = fmaxf(mval, sc);
            const float corr = __expf(mval - mn);
            const float p = __expf(sc - mn);
            l = l * corr + p;
            const float4* vr = (const float4*)&gvs[j * 64];
#pragma unroll
            for (int d4 = 0; d4 < 16; d4++) {
                const float4 vv = vr[d4];
                acc[d4*4+0] = acc[d4*4+0] * corr + p * vv.x;
                acc[d4*4+1] = acc[d4*4+1] * corr + p * vv.y;
                acc[d4*4+2] = acc[d4*4+2] * corr + p * vv.z;
                acc[d4*4+3] = acc[d4*4+3] * corr + p * vv.w;
            }
            mval = mn;
        }
    }

    __syncthreads();
    float* scratch = ks;
    if (half_) {
        float* sp = scratch + qi * 66;
        sp[0] = mval; sp[1] = l;
#pragma unroll
        for (int d = 0; d < 64; d++) sp[2 + d] = acc[d];
    }
    __syncthreads();
    if (!half_ && s >= NGG) {
        const float* sp = scratch + qi * 66;
        const float m1 = sp[0], l1 = sp[1];
        const float mh = fmaxf(mval, m1);
        const float c0 = __expf(mval - mh);
        const float c1 = __expf(m1 - mh);
        const float inv = 1.f / (l * c0 + l1 * c1);
        const size_t ob = ((size_t)(b * SS + s)) * DDIM + h * DH;
#pragma unroll
        for (int d = 0; d < 64; d += 2) {
            const float v0 = (acc[d]     * c0 + sp[2 + d]     * c1) * inv;
            const float v1 = (acc[d + 1] * c0 + sp[2 + d + 1] * c1) * inv;
            *(__half2*)&ctx16[ob + d] = __floats2half2_rn(v0, v1);
        }
    }
}

// ---------------- global-row attention --------------------------------------
__global__ __launch_bounds__(128)
void global_attn(const float* __restrict__ q, const float* __restrict__ k,
                 const float* __restrict__ v, const float* __restrict__ am,
                 __half* __restrict__ ctx16)
{
    __shared__ float lg[SS];
    __shared__ float qs[64];
    __shared__ float red[128];

    const int g = blockIdx.x, bh = blockIdx.y;
    const int b = bh / NHH, h = bh % NHH;
    const int tid = threadIdx.x;

    if (tid < 64) qs[tid] = q[((size_t)bh * SS + g) * DH + tid];
    __syncthreads();

    const float* kb = k + (size_t)bh * SS * DH;
    for (int s = tid; s < SS; s += 128) {
        const float4* kr = (const float4*)&kb[(size_t)s * DH];
        float s0 = 0.f, s1 = 0.f, s2 = 0.f, s3 = 0.f;
#pragma unroll
        for (int d4 = 0; d4 < 16; d4++) {
            const float4 kv = kr[d4];
            s0 += qs[d4 * 4 + 0] * kv.x;
            s1 += qs[d4 * 4 + 1] * kv.y;
            s2 += qs[d4 * 4 + 2] * kv.z;
            s3 += qs[d4 * 4 + 3] * kv.w;
        }
        lg[s] = (s0 + s1) + (s2 + s3) + am[b * SS + s];
    }
    __syncthreads();

    float mx = -1e30f;
    for (int s = tid; s < SS; s += 128) mx = fmaxf(mx, lg[s]);
    red[tid] = mx;
    __syncthreads();
    for (int st = 64; st > 0; st >>= 1) {
        if (tid < st) red[tid] = fmaxf(red[tid], red[tid + st]);
        __syncthreads();
    }
    mx = red[0];
    __syncthreads();

    float sum = 0.f;
    for (int s = tid; s < SS; s += 128) {
        const float e = __expf(lg[s] - mx);
        lg[s] = e;
        sum += e;
    }
    red[tid] = sum;
    __syncthreads();
    for (int st = 64; st > 0; st >>= 1) {
        if (tid < st) red[tid] += red[tid + st];
        __syncthreads();
    }
    const float inv = 1.f / red[0];
    __syncthreads();

    const float* vb = v + (size_t)bh * SS * DH;
    const int d = tid & 63, half_ = tid >> 6;
    float acc = 0.f;
    const int s0 = half_ * (SS / 2), s1 = s0 + SS / 2;
    for (int s = s0; s < s1; s++)
        acc += lg[s] * vb[(size_t)s * DH + d];
    red[tid] = acc;
    __syncthreads();
    if (tid < 64) {
        const float val = (red[tid] + red[tid + 64]) * inv;
        ctx16[((size_t)(b * SS + g)) * DDIM + h * DH + d] = __float2half(val);
    }
}

// ---------------- layernorm (optional fp16 side output) ---------------------
__global__ __launch_bounds__(256)
void layernorm_k(const float* __restrict__ X, const float* __restrict__ gw,
                 const float* __restrict__ bw, float* __restrict__ Y,
                 __half* __restrict__ Yh)
{
    __shared__ float xs[DDIM];
    __shared__ float red[256];
    const int row = blockIdx.x, tid = threadIdx.x;
    const float* xp = X + (size_t)row * DDIM;

    float sum = 0.f;
    for (int i = tid; i < DDIM; i += 256) { const float t = xp[i]; xs[i] = t; sum += t; }
    red[tid] = sum;
    __syncthreads();
    for (int st = 128; st > 0; st >>= 1) {
        if (tid < st) red[tid] += red[tid + st];
        __syncthreads();
    }
    const float mu = red[0] * (1.f / DDIM);
    __syncthreads();

    float vsum = 0.f;
    for (int i = tid; i < DDIM; i += 256) { const float d = xs[i] - mu; vsum += d * d; }
    red[tid] = vsum;
    __syncthreads();
    for (int st = 128; st > 0; st >>= 1) {
        if (tid < st) red[tid] += red[tid + st];
        __syncthreads();
    }
    const float rstd = rsqrtf(red[0] * (1.f / DDIM) + 1e-12f);
    for (int i = tid; i < DDIM; i += 256) {
        const float val = (xs[i] - mu) * rstd * gw[i] + bw[i];
        Y[(size_t)row * DDIM + i] = val;
        if (Yh) Yh[(size_t)row * DDIM + i] = __float2half(val);
    }
}

// ---------------- launch ----------------------------------------------------
extern "C" void kernel_launch(void* const* d_in, const int* in_sizes, int n_in,
                              void* d_out, int out_size)
{
    const float* h    = (const float*)d_in[0];
    const float* am   = (const float*)d_in[1];
    const float* Wq   = (const float*)d_in[2];
    const float* bq   = (const float*)d_in[3];
    const float* Wk   = (const float*)d_in[4];
    const float* bk   = (const float*)d_in[5];
    const float* Wv   = (const float*)d_in[6];
    const float* bv   = (const float*)d_in[7];
    const float* Wo   = (const float*)d_in[8];
    const float* bo   = (const float*)d_in[9];
    const float* ln1g = (const float*)d_in[10];
    const float* ln1b = (const float*)d_in[11];
    const float* Wi   = (const float*)d_in[12];
    const float* bi   = (const float*)d_in[13];
    const float* Wo2  = (const float*)d_in[14];
    const float* bo2  = (const float*)d_in[15];
    const float* ln2g = (const float*)d_in[16];
    const float* ln2b = (const float*)d_in[17];

    float *q, *k, *v, *x1, *attn, *x2;
    __half *h16, *ctx16, *at16, *in16, *wqkvt, *wot, *wit, *wo2t;
    cudaGetSymbolAddress((void**)&q,    g_q);
    cudaGetSymbolAddress((void**)&k,    g_k);
    cudaGetSymbolAddress((void**)&v,    g_v);
    cudaGetSymbolAddress((void**)&x1,   g_x1);
    cudaGetSymbolAddress((void**)&attn, g_attn);
    cudaGetSymbolAddress((void**)&x2,   g_x2);
    cudaGetSymbolAddress((void**)&h16,  g_h16);
    cudaGetSymbolAddress((void**)&ctx16,g_ctx16);
    cudaGetSymbolAddress((void**)&at16, g_at16);
    cudaGetSymbolAddress((void**)&in16, g_in16);
    cudaGetSymbolAddress((void**)&wqkvt,g_wqkvt);
    cudaGetSymbolAddress((void**)&wot,  g_wot);
    cudaGetSymbolAddress((void**)&wit,  g_wit);
    cudaGetSymbolAddress((void**)&wo2t, g_wo2t);

    cudaFuncSetAttribute(local_attn, cudaFuncAttributeMaxDynamicSharedMemorySize, (int)LOC_SMEM);
    cudaFuncSetAttribute(gemm_f16<EP_QKV>,  cudaFuncAttributeMaxDynamicSharedMemorySize, SMEM16);
    cudaFuncSetAttribute(gemm_f16<EP_RES>,  cudaFuncAttributeMaxDynamicSharedMemorySize, SMEM16);
    cudaFuncSetAttribute(gemm_f16<EP_GELU>, cudaFuncAttributeMaxDynamicSharedMemorySize, SMEM16);

    // --- prepare fp16 operands ---
    convert_f16<<<(MM * DDIM / 4 + 255) / 256, 256>>>(h, h16, MM * DDIM / 4);
    transpose_f16<<<dim3(DDIM / 32, DDIM / 32), 256>>>(Wq, wqkvt,                DDIM, DDIM);
    transpose_f16<<<dim3(DDIM / 32, DDIM / 32), 256>>>(Wk, wqkvt + DDIM * DDIM,  DDIM, DDIM);
    transpose_f16<<<dim3(DDIM / 32, DDIM / 32), 256>>>(Wv, wqkvt + 2*DDIM*DDIM,  DDIM, DDIM);
    transpose_f16<<<dim3(DDIM / 32, DDIM / 32), 256>>>(Wo, wot, DDIM, DDIM);
    transpose_f16<<<dim3(FF / 32,   DDIM / 32), 256>>>(Wi,  wit,  DDIM, FF);
    transpose_f16<<<dim3(DDIM / 32, FF / 32),   256>>>(Wo2, wo2t, FF, DDIM);

    // --- merged QKV projection (N = 2304) ---
    gemm_f16<EP_QKV><<<dim3(3 * DDIM / 128, MM / 128), 256, SMEM16>>>(
        h16, wqkvt, bq, bk, bv, nullptr, q, k, v, nullptr, MM, 3 * DDIM, DDIM);

    // --- attention ---
    local_attn<<<dim3(CC, BB * NHH), 256, LOC_SMEM>>>(q, k, v, am, ctx16);
    global_attn<<<dim3(NGG, BB * NHH), 128>>>(q, k, v, am, ctx16);

    // --- output projection + residual, LN1 ---
    gemm_f16<EP_RES><<<dim3(DDIM / 128, MM / 128), 256, SMEM16>>>(
        ctx16, wot, bo, nullptr, nullptr, h, x1, nullptr, nullptr, nullptr, MM, DDIM, DDIM);
    layernorm_k<<<MM, 256>>>(x1, ln1g, ln1b, attn, at16);

    // --- FFN ---
    gemm_f16<EP_GELU><<<dim3(FF / 128, MM / 128), 256, SMEM16>>>(
        at16, wit, bi, nullptr, nullptr, nullptr, nullptr, nullptr, nullptr, in16, MM, FF, DDIM);
    gemm_f16<EP_RES><<<dim3(DDIM / 128, MM / 128), 256, SMEM16>>>(
        in16, wo2t, bo2, nullptr, nullptr, attn, x2, nullptr, nullptr, nullptr, MM, DDIM, FF);
    layernorm_k<<<MM, 256>>>(x2, ln2g, ln2b, (float*)d_out, nullptr);
}

// round 14
// speedup vs baseline: 4.0817x; 1.1718x over previous
#include <cuda_runtime.h>
#include <cuda_fp16.h>
#include <math.h>
#include <stdint.h>

// ---------------- problem constants ----------------
#define BB   2
#define SS   4096
#define DDIM 768
#define FF   3072
#define NHH  12
#define DH   64
#define WW   128
#define NGG  32
#define CC   (SS/WW)
#define MM   (BB*SS)

// ---------------- scratch ----------------
__device__ float g_q   [BB*NHH*SS*DH];   // q; later FFN2 partial P1
__device__ float g_k   [BB*NHH*SS*DH];   // k; later out-proj partial P1
__device__ float g_v   [BB*NHH*SS*DH];
__device__ float g_x1  [MM*DDIM];        // FFN2 partial P0
__device__ float g_x2  [MM*DDIM];        // out-proj partial P0
__device__ float g_attn[MM*DDIM];

__device__ __half g_h16  [MM*DDIM];
__device__ __half g_ctx16[MM*DDIM];
__device__ __half g_at16 [MM*DDIM];
__device__ __half g_in16 [(size_t)MM*FF];

__device__ __half g_wqkvt[3*DDIM*DDIM];   // [2304][768]
__device__ __half g_wot  [DDIM*DDIM];
__device__ __half g_wit  [DDIM*FF];       // [3072][768]
__device__ __half g_wo2t [DDIM*FF];       // [768][3072]

#define GSPLIT 16
#define GKEYS  (SS/GSPLIT)                // 256
__device__ float g_gsc[BB*NHH*GSPLIT*NGG*66];   // global-attn partials

// ================= helpers =================
__device__ __forceinline__ uint32_t smem_u32(const void* p) {
    uint32_t a;
    asm("{ .reg .u64 t; cvta.to.shared.u64 t, %1; cvt.u32.u64 %0, t; }" : "=r"(a) : "l"(p));
    return a;
}
__device__ __forceinline__ void cpa16(uint32_t s, const void* g) {
    asm volatile("cp.async.cg.shared.global [%0], [%1], 16;\n" :: "r"(s), "l"(g));
}
__device__ __forceinline__ void ldsm4(uint32_t& r0, uint32_t& r1, uint32_t& r2, uint32_t& r3,
                                      uint32_t addr) {
    asm volatile("ldmatrix.sync.aligned.m8n8.x4.shared.b16 {%0,%1,%2,%3}, [%4];"
                 : "=r"(r0), "=r"(r1), "=r"(r2), "=r"(r3) : "r"(addr));
}
__device__ __forceinline__ void mma_f16(float* c, const uint32_t* a, const uint32_t* b) {
    asm volatile("mma.sync.aligned.m16n8k16.row.col.f32.f16.f16.f32 "
                 "{%0,%1,%2,%3}, {%4,%5,%6,%7}, {%8,%9}, {%0,%1,%2,%3};"
                 : "+f"(c[0]), "+f"(c[1]), "+f"(c[2]), "+f"(c[3])
                 : "r"(a[0]), "r"(a[1]), "r"(a[2]), "r"(a[3]), "r"(b[0]), "r"(b[1]));
}
__device__ __forceinline__ uint32_t swz(int row, int c16) {
    return (uint32_t)row * 128 + (uint32_t)(((c16 ^ (row & 7)) & 7) * 16);
}

// ================= fp16 GEMM: C[M,N] = A[M,K] @ B[N,K]^T ====================
// Tile 128x128, K-chunk 64, 3-stage cp.async, one sync per chunk, 2 CTAs/SM.
// blockIdx.z = K-split index (Ksplit elements each, row stride Kstride).
#define EP_QKV   0
#define EP_GELU  1
#define EP_PART  2   // raw fp32 partial (split-K)
#define NSTG 3
#define MAT_B16 (128*64*2)
#define STG16   (2*MAT_B16)
#define SMEM16  (NSTG*STG16)        // 96 KB

template<int MODE>
__global__ __launch_bounds__(256, 2)
void gemm_f16(const __half* __restrict__ A, const __half* __restrict__ B,
              const float* __restrict__ biasQ, const float* __restrict__ biasK,
              const float* __restrict__ biasV,
              float* __restrict__ C0, float* __restrict__ C1, float* __restrict__ C2,
              __half* __restrict__ Ch, int M, int N, int Ksplit, int Kstride)
{
    extern __shared__ char smem[];
    const uint32_t sdata = smem_u32(smem);
    const int tid = threadIdx.x;
    const int wid = tid >> 5, lane = tid & 31;
    const int warp_m = wid & 1;
    const int warp_n = wid >> 1;
    const int m0 = blockIdx.y * 128, n0 = blockIdx.x * 128;
    const int kbase = blockIdx.z * Ksplit;

    const int aRow   = lane & 15;
    const int aChunk = lane >> 4;
    const int bRow   = (lane & 7) + ((lane >> 4) << 3);
    const int bChunk = (lane >> 3) & 1;

    float acc[4][4][4];
#pragma unroll
    for (int i = 0; i < 4; i++)
#pragma unroll
        for (int j = 0; j < 4; j++)
#pragma unroll
            for (int t = 0; t < 4; t++) acc[i][j][t] = 0.f;

    const int r  = tid >> 1;
    const int cg = (tid & 1) * 4;

    auto load_stage = [&](int buf, int k0) {
        const uint32_t sb = sdata + buf * STG16;
        const size_t ao = (size_t)(m0 + r) * Kstride + kbase + k0;
        const size_t bo = (size_t)(n0 + r) * Kstride + kbase + k0;
#pragma unroll
        for (int cc = 0; cc < 4; cc++) {
            const int c = cg + cc;
            const uint32_t off = swz(r, c);
            cpa16(sb + off,           A + ao + c * 8);
            cpa16(sb + MAT_B16 + off, B + bo + c * 8);
        }
        asm volatile("cp.async.commit_group;" ::: "memory");
    };

    const int NK = Ksplit / 64;
    load_stage(0, 0);
    load_stage(1, 64);

    for (int j = 0; j < NK; j++) {
        if (j == NK - 1) asm volatile("cp.async.wait_group 0;" ::: "memory");
        else             asm volatile("cp.async.wait_group 1;" ::: "memory");
        __syncthreads();

        const uint32_t sb = sdata + (j % NSTG) * STG16;
        const uint32_t sA = sb, sB = sb + MAT_B16;

#pragma unroll
        for (int s = 0; s < 4; s++) {
            const int c0 = 2 * s;
            uint32_t bf[4][2];
#pragma unroll
            for (int bt = 0; bt < 2; bt++) {
                const int nrow = warp_n * 32 + bt * 16 + bRow;
                ldsm4(bf[2*bt][0], bf[2*bt][1], bf[2*bt+1][0], bf[2*bt+1][1],
                      sB + swz(nrow, c0 + bChunk));
            }
#pragma unroll
            for (int mt = 0; mt < 4; mt++) {
                const int arow = warp_m * 64 + mt * 16 + aRow;
                uint32_t ah[4];
                ldsm4(ah[0], ah[1], ah[2], ah[3], sA + swz(arow, c0 + aChunk));
#pragma unroll
                for (int nt = 0; nt < 4; nt++)
                    mma_f16(acc[mt][nt], ah, bf[nt]);
            }
        }
        if (j + 2 < NK) load_stage((j + 2) % NSTG, (j + 2) * 64);
    }

    // ---------------- epilogue ----------------
    const int rbase = lane >> 2;
    const int cbase = (lane & 3) * 2;

    const float* bs = biasQ;
    float* Cq = C0;
    float qscale = 1.f;
    int nsub = 0;
    if (MODE == EP_QKV) {
        const int which = n0 / DDIM;
        bs = (which == 0) ? biasQ : (which == 1) ? biasK : biasV;
        Cq = (which == 0) ? C0 : (which == 1) ? C1 : C2;
        qscale = (which == 0) ? 0.125f : 1.f;
        nsub = which * DDIM;
    }
    float* Pp = (MODE == EP_PART) ? (blockIdx.z ? C1 : C0) : C0;

#pragma unroll
    for (int mt = 0; mt < 4; mt++) {
#pragma unroll
        for (int half_ = 0; half_ < 2; half_++) {
            const int m = m0 + warp_m * 64 + mt * 16 + rbase + half_ * 8;
            const int bidx = m >> 12, srow = m & (SS - 1);
#pragma unroll
            for (int nt = 0; nt < 4; nt++) {
                const int n = n0 + warp_n * 32 + nt * 8 + cbase;
                const float v0r = acc[mt][nt][half_ * 2 + 0];
                const float v1r = acc[mt][nt][half_ * 2 + 1];
                if (MODE == EP_QKV) {
                    const int nrel = n - nsub;
                    const int hh = nrel >> 6, d0 = nrel & 63;
                    float2 vv;
                    vv.x = (v0r + bs[nrel])     * qscale;
                    vv.y = (v1r + bs[nrel + 1]) * qscale;
                    *(float2*)&Cq[(((size_t)(bidx * NHH + hh)) * SS + srow) * DH + d0] = vv;
                } else if (MODE == EP_PART) {
                    const size_t o = (size_t)m * N + n;
                    *(float2*)&Pp[o] = make_float2(v0r, v1r);
                } else { // EP_GELU -> fp16
                    float v0 = v0r + biasQ[n];
                    float v1 = v1r + biasQ[n + 1];
                    v0 = 0.5f * v0 * (1.f + erff(v0 * 0.70710678118654752f));
                    v1 = 0.5f * v1 * (1.f + erff(v1 * 0.70710678118654752f));
                    const size_t o = (size_t)m * N + n;
                    *(__half2*)&Ch[o] = __floats2half2_rn(v0, v1);
                }
            }
        }
    }
}

// ---------------- convert fp32 -> fp16 --------------------------------------
__global__ __launch_bounds__(256)
void convert_f16(const float* __restrict__ X, __half* __restrict__ H, int n4)
{
    const int i = blockIdx.x * 256 + threadIdx.x;
    if (i >= n4) return;
    const float4 v = ((const float4*)X)[i];
    ((__half2*)H)[i * 2 + 0] = __floats2half2_rn(v.x, v.y);
    ((__half2*)H)[i * 2 + 1] = __floats2half2_rn(v.z, v.w);
}

// ---------------- transpose fp32 [K,N] -> fp16 [N,K] ------------------------
__global__ __launch_bounds__(256)
void transpose_f16(const float* __restrict__ W, __half* __restrict__ T, int K, int N)
{
    __shared__ float t[32][33];
    const int nb = blockIdx.x * 32, kb = blockIdx.y * 32;
    const int tx = threadIdx.x & 31, ty = (threadIdx.x >> 5) * 4;
#pragma unroll
    for (int i = 0; i < 4; i++)
        t[ty + i][tx] = W[(size_t)(kb + ty + i) * N + nb + tx];
    __syncthreads();
#pragma unroll
    for (int i = 0; i < 4; i++)
        T[(size_t)(nb + ty + i) * K + kb + tx] = __float2half(t[tx][ty + i]);
}

// ---------------- local (banded) attention: split-key, 256 threads ----------
#define LOC_SMEM ((384*64*2 + 32*64*2 + 384 + 32) * sizeof(float))

__global__ __launch_bounds__(256)
void local_attn(const float* __restrict__ q, const float* __restrict__ k,
                const float* __restrict__ v, const float* __restrict__ am,
                __half* __restrict__ ctx16)
{
    extern __shared__ float sm[];
    float* ks  = sm;
    float* vs  = ks + 384 * 64;
    float* gks = vs + 384 * 64;
    float* gvs = gks + 32 * 64;
    float* ams = gvs + 32 * 64;

    const int c = blockIdx.x, bh = blockIdx.y;
    const int b = bh / NHH, h = bh % NHH;
    const int tid = threadIdx.x;
    const int qi = tid & 127, half_ = tid >> 7;
    const float* kb = k + (size_t)bh * SS * DH;
    const float* vb = v + (size_t)bh * SS * DH;
    const int base = c * WW - WW;

    for (int i = tid; i < 384 * 64; i += 256) {
        const int j = i >> 6, d = i & 63;
        const int kp = base + j;
        const bool in = (kp >= 0 && kp < SS);
        ks[i] = in ? kb[(size_t)kp * DH + d] : 0.f;
        vs[i] = in ? vb[(size_t)kp * DH + d] : 0.f;
    }
    for (int i = tid; i < 32 * 64; i += 256) { gks[i] = kb[i]; gvs[i] = vb[i]; }
    for (int j = tid; j < 384; j += 256) {
        const int kp = base + j;
        ams[j] = (kp >= 0 && kp < SS) ? am[b * SS + kp] : 0.f;
    }
    if (tid < 32) ams[384 + tid] = am[b * SS + tid];
    __syncthreads();

    const int s = c * WW + qi;
    float qr[64];
    const float* qp = q + ((size_t)bh * SS + s) * DH;
#pragma unroll
    for (int d = 0; d < 64; d += 4) {
        float4 t = *(const float4*)&qp[d];
        qr[d] = t.x; qr[d + 1] = t.y; qr[d + 2] = t.z; qr[d + 3] = t.w;
    }

    float mval = -1e30f, l = 0.f;
    float acc[64];
#pragma unroll
    for (int d = 0; d < 64; d++) acc[d] = 0.f;

    const int j0 = half_ ? 192 : 0;
    const int j1 = half_ ? 384 : 192;
    for (int j = j0; j < j1; j++) {
        const int kp = base + j;
        const int dlt = kp - s;
        if (dlt < -WW || dlt > WW || kp < NGG || kp >= SS) continue;
        const float4* kr = (const float4*)&ks[j * 64];
        float s0 = 0.f, s1 = 0.f, s2 = 0.f, s3 = 0.f;
#pragma unroll
        for (int d4 = 0; d4 < 16; d4++) {
            const float4 kv = kr[d4];
            s0 += qr[d4*4+0] * kv.x;
            s1 += qr[d4*4+1] * kv.y;
            s2 += qr[d4*4+2] * kv.z;
            s3 += qr[d4*4+3] * kv.w;
        }
        const float sc = (s0 + s1) + (s2 + s3) + ams[j];
        const float mn = fmaxf(mval, sc);
        const float corr = __expf(mval - mn);
        const float p = __expf(sc - mn);
        l = l * corr + p;
        const float4* vr = (const float4*)&vs[j * 64];
#pragma unroll
        for (int d4 = 0; d4 < 16; d4++) {
            const float4 vv = vr[d4];
            acc[d4*4+0] = acc[d4*4+0] * corr + p * vv.x;
            acc[d4*4+1] = acc[d4*4+1] * corr + p * vv.y;
            acc[d4*4+2] = acc[d4*4+2] * corr + p * vv.z;
            acc[d4*4+3] = acc[d4*4+3] * corr + p * vv.w;
        }
        mval = mn;
    }
    if (half_) {
        for (int j = 0; j < 32; j++) {
            const float4* kr = (const float4*)&gks[j * 64];
            float s0 = 0.f, s1 = 0.f, s2 = 0.f, s3 = 0.f;
#pragma unroll
            for (int d4 = 0; d4 < 16; d4++) {
                const float4 kv = kr[d4];
                s0 += qr[d4*4+0] * kv.x;
                s1 += qr[d4*4+1] * kv.y;
                s2 += qr[d4*4+2] * kv.z;
                s3 += qr[d4*4+3] * kv.w;
            }
            const float sc = (s0 + s1) + (s2 + s3) + ams[384 + j];
            const float mn = fmaxf(mval, sc);
            const float corr = __expf(mval - mn);
            const float p = __expf(sc - mn);
            l = l * corr + p;
            const float4* vr = (const float4*)&gvs[j * 64];
#pragma unroll
            for (int d4 = 0; d4 < 16; d4++) {
                const float4 vv = vr[d4];
                acc[d4*4+0] = acc[d4*4+0] * corr + p * vv.x;
                acc[d4*4+1] = acc[d4*4+1] * corr + p * vv.y;
                acc[d4*4+2] = acc[d4*4+2] * corr + p * vv.z;
                acc[d4*4+3] = acc[d4*4+3] * corr + p * vv.w;
            }
            mval = mn;
        }
    }

    __syncthreads();
    float* scratch = ks;
    if (half_) {
        float* sp = scratch + qi * 66;
        sp[0] = mval; sp[1] = l;
#pragma unroll
        for (int d = 0; d < 64; d++) sp[2 + d] = acc[d];
    }
    __syncthreads();
    if (!half_ && s >= NGG) {
        const float* sp = scratch + qi * 66;
        const float m1 = sp[0], l1 = sp[1];
        const float mh = fmaxf(mval, m1);
        const float c0 = __expf(mval - mh);
        const float c1 = __expf(m1 - mh);
        const float inv = 1.f / (l * c0 + l1 * c1);
        const size_t ob = ((size_t)(b * SS + s)) * DDIM + h * DH;
#pragma unroll
        for (int d = 0; d < 64; d += 2) {
            const float v0 = (acc[d]     * c0 + sp[2 + d]     * c1) * inv;
            const float v1 = (acc[d + 1] * c0 + sp[2 + d + 1] * c1) * inv;
            *(__half2*)&ctx16[ob + d] = __floats2half2_rn(v0, v1);
        }
    }
}

// ---------------- global-row attention, phase 1: per-key-split partials -----
// block (split, bh): K/V tile of 256 keys in smem, serves ALL 32 global rows.
// thread (row, seg): row = tid&31, seg = tid>>5; seg covers 32 keys.
#define GPA_SMEM ((GKEYS*64*2 + 32*65 + GKEYS) * sizeof(float))

__global__ __launch_bounds__(256)
void global_attn_part(const float* __restrict__ q, const float* __restrict__ k,
                      const float* __restrict__ v, const float* __restrict__ am,
                      float* __restrict__ gsc)
{
    extern __shared__ float sm[];
    float* ks  = sm;                    // [256][64]
    float* vs  = ks + GKEYS * 64;       // [256][64]
    float* qs  = vs + GKEYS * 64;       // [32][65] padded
    float* ams = qs + 32 * 65;          // [256]

    const int sp = blockIdx.x, bh = blockIdx.y;
    const int b = bh / NHH;
    const int tid = threadIdx.x;
    const int base = sp * GKEYS;
    const float* kb = k + (size_t)bh * SS * DH;
    const float* vb = v + (size_t)bh * SS * DH;

    for (int i = tid; i < GKEYS * 64; i += 256) {
        ks[i] = kb[(size_t)base * 64 + i];
        vs[i] = vb[(size_t)base * 64 + i];
    }
    for (int i = tid; i < 32 * 64; i += 256)
        qs[(i >> 6) * 65 + (i & 63)] = q[(size_t)bh * SS * DH + i];
    if (tid < GKEYS) ams[tid] = am[b * SS + base + tid];
    __syncthreads();

    const int row = tid & 31, seg = tid >> 5;
    float qr[64];
#pragma unroll
    for (int d = 0; d < 64; d++) qr[d] = qs[row * 65 + d];

    float mval = -1e30f, l = 0.f;
    float acc[64];
#pragma unroll
    for (int d = 0; d < 64; d++) acc[d] = 0.f;

    const int jj0 = seg * 32, jj1 = jj0 + 32;
    for (int j = jj0; j < jj1; j++) {
        const float4* kr = (const float4*)&ks[j * 64];
        float s0 = 0.f, s1 = 0.f, s2 = 0.f, s3 = 0.f;
#pragma unroll
        for (int d4 = 0; d4 < 16; d4++) {
            const float4 kv = kr[d4];
            s0 += qr[d4*4+0] * kv.x;
            s1 += qr[d4*4+1] * kv.y;
            s2 += qr[d4*4+2] * kv.z;
            s3 += qr[d4*4+3] * kv.w;
        }
        const float sc = (s0 + s1) + (s2 + s3) + ams[j];
        const float mn = fmaxf(mval, sc);
        const float corr = __expf(mval - mn);
        const float p = __expf(sc - mn);
        l = l * corr + p;
        const float4* vr = (const float4*)&vs[j * 64];
#pragma unroll
        for (int d4 = 0; d4 < 16; d4++) {
            const float4 vv = vr[d4];
            acc[d4*4+0] = acc[d4*4+0] * corr + p * vv.x;
            acc[d4*4+1] = acc[d4*4+1] * corr + p * vv.y;
            acc[d4*4+2] = acc[d4*4+2] * corr + p * vv.z;
            acc[d4*4+3] = acc[d4*4+3] * corr + p * vv.w;
        }
        mval = mn;
    }

    // merge 8 segs per row via smem (ks region dead)
    __syncthreads();
    float* scr = ks;                    // [32][8][66]
    float* sp_ = scr + (row * 8 + seg) * 66;
    sp_[0] = mval; sp_[1] = l;
#pragma unroll
    for (int d = 0; d < 64; d++) sp_[2 + d] = acc[d];
    __syncthreads();

    if (seg == 0) {
        float mstar = -1e30f;
#pragma unroll
        for (int t = 0; t < 8; t++) mstar = fmaxf(mstar, scr[(row * 8 + t) * 66]);
        float lstar = 0.f;
        float out[64];
#pragma unroll
        for (int d = 0; d < 64; d++) out[d] = 0.f;
#pragma unroll
        for (int t = 0; t < 8; t++) {
            const float* pp = scr + (row * 8 + t) * 66;
            const float w = __expf(pp[0] - mstar);
            lstar += pp[1] * w;
#pragma unroll
            for (int d = 0; d < 64; d++) out[d] += pp[2 + d] * w;
        }
        float* gp = gsc + (((size_t)bh * GSPLIT + sp) * NGG + row) * 66;
        gp[0] = mstar; gp[1] = lstar;
#pragma unroll
        for (int d = 0; d < 64; d++) gp[2 + d] = out[d];
    }
}

// ---------------- global-row attention, phase 2: merge splits ---------------
__global__ __launch_bounds__(256)
void global_attn_merge(const float* __restrict__ gsc, __half* __restrict__ ctx16)
{
    const int bh = blockIdx.x;
    const int b = bh / NHH, h = bh % NHH;
    const int tid = threadIdx.x;
    const int row = tid >> 3, dc = (tid & 7) * 8;

    const float* rp = gsc + ((size_t)bh * GSPLIT * NGG + row) * 66;
    float mstar = -1e30f;
#pragma unroll
    for (int s = 0; s < GSPLIT; s++)
        mstar = fmaxf(mstar, rp[(size_t)s * NGG * 66]);
    float lstar = 0.f;
    float out[8];
#pragma unroll
    for (int d = 0; d < 8; d++) out[d] = 0.f;
#pragma unroll
    for (int s = 0; s < GSPLIT; s++) {
        const float* pp = rp + (size_t)s * NGG * 66;
        const float w = __expf(pp[0] - mstar);
        lstar += pp[1] * w;
#pragma unroll
        for (int d = 0; d < 8; d++) out[d] += pp[2 + dc + d] * w;
    }
    const float inv = 1.f / lstar;
    const size_t ob = ((size_t)(b * SS + row)) * DDIM + h * DH + dc;
#pragma unroll
    for (int d = 0; d < 8; d += 2)
        *(__half2*)&ctx16[ob + d] = __floats2half2_rn(out[d] * inv, out[d + 1] * inv);
}

// ---------------- layernorm with fused combine: LN(P0+P1+Res+bias) ----------
__global__ __launch_bounds__(256)
void ln_combine(const float* __restrict__ P0, const float* __restrict__ P1,
                const float* __restrict__ Res, const float* __restrict__ bias,
                const float* __restrict__ gw, const float* __restrict__ bw,
                float* __restrict__ Y, __half* __restrict__ Yh)
{
    __shared__ float xs[DDIM];
    __shared__ float red[256];
    const int row = blockIdx.x, tid = threadIdx.x;
    const size_t bo = (size_t)row * DDIM;

    float sum = 0.f;
    for (int i = tid; i < DDIM; i += 256) {
        const float t = P0[bo + i] + P1[bo + i] + Res[bo + i] + bias[i];
        xs[i] = t; sum += t;
    }
    red[tid] = sum;
    __syncthreads();
    for (int st = 128; st > 0; st >>= 1) {
        if (tid < st) red[tid] += red[tid + st];
        __syncthreads();
    }
    const float mu = red[0] * (1.f / DDIM);
    __syncthreads();

    float vsum = 0.f;
    for (int i = tid; i < DDIM; i += 256) { const float d = xs[i] - mu; vsum += d * d; }
    red[tid] = vsum;
    __syncthreads();
    for (int st = 128; st > 0; st >>= 1) {
        if (tid < st) red[tid] += red[tid + st];
        __syncthreads();
    }
    const float rstd = rsqrtf(red[0] * (1.f / DDIM) + 1e-12f);
    for (int i = tid; i < DDIM; i += 256) {
        const float val = (xs[i] - mu) * rstd * gw[i] + bw[i];
        Y[bo + i] = val;
        if (Yh) Yh[bo + i] = __float2half(val);
    }
}

// ---------------- launch ----------------------------------------------------
extern "C" void kernel_launch(void* const* d_in, const int* in_sizes, int n_in,
                              void* d_out, int out_size)
{
    const float* h    = (const float*)d_in[0];
    const float* am   = (const float*)d_in[1];
    const float* Wq   = (const float*)d_in[2];
    const float* bq   = (const float*)d_in[3];
    const float* Wk   = (const float*)d_in[4];
    const float* bk   = (const float*)d_in[5];
    const float* Wv   = (const float*)d_in[6];
    const float* bv   = (const float*)d_in[7];
    const float* Wo   = (const float*)d_in[8];
    const float* bo   = (const float*)d_in[9];
    const float* ln1g = (const float*)d_in[10];
    const float* ln1b = (const float*)d_in[11];
    const float* Wi   = (const float*)d_in[12];
    const float* bi   = (const float*)d_in[13];
    const float* Wo2  = (const float*)d_in[14];
    const float* bo2  = (const float*)d_in[15];
    const float* ln2g = (const float*)d_in[16];
    const float* ln2b = (const float*)d_in[17];

    float *q, *k, *v, *x1, *x2, *attn, *gsc;
    __half *h16, *ctx16, *at16, *in16, *wqkvt, *wot, *wit, *wo2t;
    cudaGetSymbolAddress((void**)&q,    g_q);
    cudaGetSymbolAddress((void**)&k,    g_k);
    cudaGetSymbolAddress((void**)&v,    g_v);
    cudaGetSymbolAddress((void**)&x1,   g_x1);
    cudaGetSymbolAddress((void**)&x2,   g_x2);
    cudaGetSymbolAddress((void**)&attn, g_attn);
    cudaGetSymbolAddress((void**)&gsc,  g_gsc);
    cudaGetSymbolAddress((void**)&h16,  g_h16);
    cudaGetSymbolAddress((void**)&ctx16,g_ctx16);
    cudaGetSymbolAddress((void**)&at16, g_at16);
    cudaGetSymbolAddress((void**)&in16, g_in16);
    cudaGetSymbolAddress((void**)&wqkvt,g_wqkvt);
    cudaGetSymbolAddress((void**)&wot,  g_wot);
    cudaGetSymbolAddress((void**)&wit,  g_wit);
    cudaGetSymbolAddress((void**)&wo2t, g_wo2t);

    cudaFuncSetAttribute(local_attn, cudaFuncAttributeMaxDynamicSharedMemorySize, (int)LOC_SMEM);
    cudaFuncSetAttribute(global_attn_part, cudaFuncAttributeMaxDynamicSharedMemorySize, (int)GPA_SMEM);
    cudaFuncSetAttribute(gemm_f16<EP_QKV>,  cudaFuncAttributeMaxDynamicSharedMemorySize, SMEM16);
    cudaFuncSetAttribute(gemm_f16<EP_GELU>, cudaFuncAttributeMaxDynamicSharedMemorySize, SMEM16);
    cudaFuncSetAttribute(gemm_f16<EP_PART>, cudaFuncAttributeMaxDynamicSharedMemorySize, SMEM16);

    // --- prepare fp16 operands ---
    convert_f16<<<(MM * DDIM / 4 + 255) / 256, 256>>>(h, h16, MM * DDIM / 4);
    transpose_f16<<<dim3(DDIM / 32, DDIM / 32), 256>>>(Wq, wqkvt,                DDIM, DDIM);
    transpose_f16<<<dim3(DDIM / 32, DDIM / 32), 256>>>(Wk, wqkvt + DDIM * DDIM,  DDIM, DDIM);
    transpose_f16<<<dim3(DDIM / 32, DDIM / 32), 256>>>(Wv, wqkvt + 2*DDIM*DDIM,  DDIM, DDIM);
    transpose_f16<<<dim3(DDIM / 32, DDIM / 32), 256>>>(Wo, wot, DDIM, DDIM);
    transpose_f16<<<dim3(FF / 32,   DDIM / 32), 256>>>(Wi,  wit,  DDIM, FF);
    transpose_f16<<<dim3(DDIM / 32, FF / 32),   256>>>(Wo2, wo2t, FF, DDIM);

    // --- merged QKV projection (N = 2304) ---
    gemm_f16<EP_QKV><<<dim3(3 * DDIM / 128, MM / 128), 256, SMEM16>>>(
        h16, wqkvt, bq, bk, bv, q, k, v, nullptr, MM, 3 * DDIM, DDIM, DDIM);

    // --- attention ---
    local_attn<<<dim3(CC, BB * NHH), 256, LOC_SMEM>>>(q, k, v, am, ctx16);
    global_attn_part<<<dim3(GSPLIT, BB * NHH), 256, GPA_SMEM>>>(q, k, v, am, gsc);
    global_attn_merge<<<BB * NHH, 256>>>(gsc, ctx16);

    // --- output projection: split-K x2 partials (k buffer is dead), LN1 fused combine ---
    gemm_f16<EP_PART><<<dim3(DDIM / 128, MM / 128, 2), 256, SMEM16>>>(
        ctx16, wot, nullptr, nullptr, nullptr, x2, k, nullptr, nullptr,
        MM, DDIM, DDIM / 2, DDIM);
    ln_combine<<<MM, 256>>>(x2, k, h, bo, ln1g, ln1b, attn, at16);

    // --- FFN ---
    gemm_f16<EP_GELU><<<dim3(FF / 128, MM / 128), 256, SMEM16>>>(
        at16, wit, bi, nullptr, nullptr, nullptr, nullptr, nullptr, in16, MM, FF, DDIM, DDIM);
    gemm_f16<EP_PART><<<dim3(DDIM / 128, MM / 128, 2), 256, SMEM16>>>(
        in16, wo2t, nullptr, nullptr, nullptr, x1, q, nullptr, nullptr,
        MM, DDIM, FF / 2, FF);
    ln_combine<<<MM, 256>>>(x1, q, attn, bo2, ln2g, ln2b, (float*)d_out, nullptr);
}

// round 17
// speedup vs baseline: 5.7831x; 1.4169x over previous
#include <cuda_runtime.h>
#include <cuda_fp16.h>
#include <math.h>
#include <stdint.h>

// ---------------- problem constants ----------------
#define BB   2
#define SS   4096
#define DDIM 768
#define FF   3072
#define NHH  12
#define DH   64
#define WW   128
#define NGG  32
#define CC   (SS/WW)
#define MM   (BB*SS)

// ---------------- scratch ----------------
__device__ float g_q   [BB*NHH*SS*DH];   // q; later FFN2 partial P1
__device__ float g_k   [BB*NHH*SS*DH];   // k; later out-proj partial P1
__device__ float g_v   [BB*NHH*SS*DH];
__device__ float g_x1  [MM*DDIM];
__device__ float g_x2  [MM*DDIM];
__device__ float g_attn[MM*DDIM];

__device__ __half g_h16  [MM*DDIM];
__device__ __half g_ctx16[MM*DDIM];
__device__ __half g_at16 [MM*DDIM];
__device__ __half g_in16 [(size_t)MM*FF];
__device__ __half g_q16  [BB*NHH*SS*DH];
__device__ __half g_k16  [BB*NHH*SS*DH];
__device__ __half g_v16  [BB*NHH*SS*DH];

__device__ __half g_wqkvt[3*DDIM*DDIM];   // [2304][768]
__device__ __half g_wot  [DDIM*DDIM];
__device__ __half g_wit  [DDIM*FF];       // [3072][768]
__device__ __half g_wo2t [DDIM*FF];       // [768][3072]

#define GSPLIT 16
#define GKEYS  (SS/GSPLIT)                // 256
__device__ float g_gsc[BB*NHH*GSPLIT*NGG*66];

// ================= helpers =================
__device__ __forceinline__ uint32_t smem_u32(const void* p) {
    uint32_t a;
    asm("{ .reg .u64 t; cvta.to.shared.u64 t, %1; cvt.u32.u64 %0, t; }" : "=r"(a) : "l"(p));
    return a;
}
__device__ __forceinline__ void cpa16(uint32_t s, const void* g) {
    asm volatile("cp.async.cg.shared.global [%0], [%1], 16;\n" :: "r"(s), "l"(g));
}
__device__ __forceinline__ void ldsm4(uint32_t& r0, uint32_t& r1, uint32_t& r2, uint32_t& r3,
                                      uint32_t addr) {
    asm volatile("ldmatrix.sync.aligned.m8n8.x4.shared.b16 {%0,%1,%2,%3}, [%4];"
                 : "=r"(r0), "=r"(r1), "=r"(r2), "=r"(r3) : "r"(addr));
}
__device__ __forceinline__ void ldsm4t(uint32_t& r0, uint32_t& r1, uint32_t& r2, uint32_t& r3,
                                       uint32_t addr) {
    asm volatile("ldmatrix.sync.aligned.m8n8.x4.trans.shared.b16 {%0,%1,%2,%3}, [%4];"
                 : "=r"(r0), "=r"(r1), "=r"(r2), "=r"(r3) : "r"(addr));
}
__device__ __forceinline__ void mma_f16(float* c, const uint32_t* a, const uint32_t* b) {
    asm volatile("mma.sync.aligned.m16n8k16.row.col.f32.f16.f16.f32 "
                 "{%0,%1,%2,%3}, {%4,%5,%6,%7}, {%8,%9}, {%0,%1,%2,%3};"
                 : "+f"(c[0]), "+f"(c[1]), "+f"(c[2]), "+f"(c[3])
                 : "r"(a[0]), "r"(a[1]), "r"(a[2]), "r"(a[3]), "r"(b[0]), "r"(b[1]));
}
__device__ __forceinline__ uint32_t swz(int row, int c16) {
    return (uint32_t)row * 128 + (uint32_t)(((c16 ^ (row & 7)) & 7) * 16);
}
__device__ __forceinline__ uint32_t packh2(float a, float b) {
    __half2 h = __floats2half2_rn(a, b);
    return *(uint32_t*)&h;
}

// ================= fp16 GEMM: C[M,N] = A[M,K] @ B[N,K]^T ====================
#define EP_QKV   0
#define EP_GELU  1
#define EP_PART  2
#define NSTG 3
#define MAT_B16 (128*64*2)
#define STG16   (2*MAT_B16)
#define SMEM16  (NSTG*STG16)        // 96 KB

template<int MODE>
__global__ __launch_bounds__(256, 2)
void gemm_f16(const __half* __restrict__ A, const __half* __restrict__ B,
              const float* __restrict__ biasQ, const float* __restrict__ biasK,
              const float* __restrict__ biasV,
              float* __restrict__ C0, float* __restrict__ C1, float* __restrict__ C2,
              __half* __restrict__ Ch, __half* __restrict__ H0, __half* __restrict__ H1,
              __half* __restrict__ H2, int M, int N, int Ksplit, int Kstride)
{
    extern __shared__ char smem[];
    const uint32_t sdata = smem_u32(smem);
    const int tid = threadIdx.x;
    const int wid = tid >> 5, lane = tid & 31;
    const int warp_m = wid & 1;
    const int warp_n = wid >> 1;
    const int m0 = blockIdx.y * 128, n0 = blockIdx.x * 128;
    const int kbase = blockIdx.z * Ksplit;

    const int aRow   = lane & 15;
    const int aChunk = lane >> 4;
    const int bRow   = (lane & 7) + ((lane >> 4) << 3);
    const int bChunk = (lane >> 3) & 1;

    float acc[4][4][4];
#pragma unroll
    for (int i = 0; i < 4; i++)
#pragma unroll
        for (int j = 0; j < 4; j++)
#pragma unroll
            for (int t = 0; t < 4; t++) acc[i][j][t] = 0.f;

    const int r  = tid >> 1;
    const int cg = (tid & 1) * 4;

    auto load_stage = [&](int buf, int k0) {
        const uint32_t sb = sdata + buf * STG16;
        const size_t ao = (size_t)(m0 + r) * Kstride + kbase + k0;
        const size_t bo = (size_t)(n0 + r) * Kstride + kbase + k0;
#pragma unroll
        for (int cc = 0; cc < 4; cc++) {
            const int c = cg + cc;
            const uint32_t off = swz(r, c);
            cpa16(sb + off,           A + ao + c * 8);
            cpa16(sb + MAT_B16 + off, B + bo + c * 8);
        }
        asm volatile("cp.async.commit_group;" ::: "memory");
    };

    const int NK = Ksplit / 64;
    load_stage(0, 0);
    load_stage(1, 64);

    for (int j = 0; j < NK; j++) {
        if (j == NK - 1) asm volatile("cp.async.wait_group 0;" ::: "memory");
        else             asm volatile("cp.async.wait_group 1;" ::: "memory");
        __syncthreads();

        const uint32_t sb = sdata + (j % NSTG) * STG16;
        const uint32_t sA = sb, sB = sb + MAT_B16;

#pragma unroll
        for (int s = 0; s < 4; s++) {
            const int c0 = 2 * s;
            uint32_t bf[4][2];
#pragma unroll
            for (int bt = 0; bt < 2; bt++) {
                const int nrow = warp_n * 32 + bt * 16 + bRow;
                ldsm4(bf[2*bt][0], bf[2*bt][1], bf[2*bt+1][0], bf[2*bt+1][1],
                      sB + swz(nrow, c0 + bChunk));
            }
#pragma unroll
            for (int mt = 0; mt < 4; mt++) {
                const int arow = warp_m * 64 + mt * 16 + aRow;
                uint32_t ah[4];
                ldsm4(ah[0], ah[1], ah[2], ah[3], sA + swz(arow, c0 + aChunk));
#pragma unroll
                for (int nt = 0; nt < 4; nt++)
                    mma_f16(acc[mt][nt], ah, bf[nt]);
            }
        }
        if (j + 2 < NK) load_stage((j + 2) % NSTG, (j + 2) * 64);
    }

    // ---------------- epilogue ----------------
    const int rbase = lane >> 2;
    const int cbase = (lane & 3) * 2;

    const float* bs = biasQ;
    float* Cq = C0;
    __half* Hq = H0;
    float qscale = 1.f;
    int nsub = 0;
    if (MODE == EP_QKV) {
        const int which = n0 / DDIM;
        bs = (which == 0) ? biasQ : (which == 1) ? biasK : biasV;
        Cq = (which == 0) ? C0 : (which == 1) ? C1 : C2;
        Hq = (which == 0) ? H0 : (which == 1) ? H1 : H2;
        qscale = (which == 0) ? 0.125f : 1.f;
        nsub = which * DDIM;
    }
    float* Pp = (MODE == EP_PART) ? (blockIdx.z ? C1 : C0) : C0;

#pragma unroll
    for (int mt = 0; mt < 4; mt++) {
#pragma unroll
        for (int half_ = 0; half_ < 2; half_++) {
            const int m = m0 + warp_m * 64 + mt * 16 + rbase + half_ * 8;
            const int bidx = m >> 12, srow = m & (SS - 1);
#pragma unroll
            for (int nt = 0; nt < 4; nt++) {
                const int n = n0 + warp_n * 32 + nt * 8 + cbase;
                const float v0r = acc[mt][nt][half_ * 2 + 0];
                const float v1r = acc[mt][nt][half_ * 2 + 1];
                if (MODE == EP_QKV) {
                    const int nrel = n - nsub;
                    const int hh = nrel >> 6, d0 = nrel & 63;
                    float2 vv;
                    vv.x = (v0r + bs[nrel])     * qscale;
                    vv.y = (v1r + bs[nrel + 1]) * qscale;
                    const size_t o = (((size_t)(bidx * NHH + hh)) * SS + srow) * DH + d0;
                    *(float2*)&Cq[o] = vv;
                    *(__half2*)&Hq[o] = __floats2half2_rn(vv.x, vv.y);
                } else if (MODE == EP_PART) {
                    const size_t o = (size_t)m * N + n;
                    *(float2*)&Pp[o] = make_float2(v0r, v1r);
                } else { // EP_GELU -> fp16
                    float v0 = v0r + biasQ[n];
                    float v1 = v1r + biasQ[n + 1];
                    v0 = 0.5f * v0 * (1.f + erff(v0 * 0.70710678118654752f));
                    v1 = 0.5f * v1 * (1.f + erff(v1 * 0.70710678118654752f));
                    const size_t o = (size_t)m * N + n;
                    *(__half2*)&Ch[o] = __floats2half2_rn(v0, v1);
                }
            }
        }
    }
}

// ---------------- convert fp32 -> fp16 --------------------------------------
__global__ __launch_bounds__(256)
void convert_f16(const float* __restrict__ X, __half* __restrict__ H, int n4)
{
    const int i = blockIdx.x * 256 + threadIdx.x;
    if (i >= n4) return;
    const float4 v = ((const float4*)X)[i];
    ((__half2*)H)[i * 2 + 0] = __floats2half2_rn(v.x, v.y);
    ((__half2*)H)[i * 2 + 1] = __floats2half2_rn(v.z, v.w);
}

// ---------------- transpose fp32 [K,N] -> fp16 [N,K] ------------------------
__global__ __launch_bounds__(256)
void transpose_f16(const float* __restrict__ W, __half* __restrict__ T, int K, int N)
{
    __shared__ float t[32][33];
    const int nb = blockIdx.x * 32, kb = blockIdx.y * 32;
    const int tx = threadIdx.x & 31, ty = (threadIdx.x >> 5) * 4;
#pragma unroll
    for (int i = 0; i < 4; i++)
        t[ty + i][tx] = W[(size_t)(kb + ty + i) * N + nb + tx];
    __syncthreads();
#pragma unroll
    for (int i = 0; i < 4; i++)
        T[(size_t)(nb + ty + i) * K + kb + tx] = __float2half(t[tx][ty + i]);
}

// ---------------- local (banded) attention: HMMA flash ----------------------
// block (chunk c, bh): Q 128x64, keys padded to 448 (384 band + 32 global + 32 pad).
// smem: Q[128][64]h swz @0, K[448][64]h swz @16384, V same @73728, ams[448]f @131072.
#define LKEYS 448
#define LA_SMEM (16384 + 2*LKEYS*128 + LKEYS*4)    // 132,864 B

__global__ __launch_bounds__(256)
void local_attn_mma(const __half* __restrict__ q16, const __half* __restrict__ k16,
                    const __half* __restrict__ v16, const float* __restrict__ am,
                    __half* __restrict__ ctx16)
{
    extern __shared__ char sm[];
    const uint32_t sb0 = smem_u32(sm);
    const uint32_t sQ = sb0, sK = sb0 + 16384, sV = sb0 + 73728;
    float* ams = (float*)(sm + 131072);

    const int c = blockIdx.x, bh = blockIdx.y;
    const int b = bh / NHH, h = bh % NHH;
    const int tid = threadIdx.x;
    const int base = c * WW - WW;
    const float NINF = __int_as_float(0xff800000);

    const __half* qb_ = q16 + ((size_t)bh * SS + c * WW) * DH;
    const __half* kb_ = k16 + (size_t)bh * SS * DH;
    const __half* vb_ = v16 + (size_t)bh * SS * DH;

    for (int idx = tid; idx < 128 * 8; idx += 256) {
        const int row = idx >> 3, c16 = idx & 7;
        *(uint4*)(sm + swz(row, c16)) = *(const uint4*)(qb_ + row * DH + c16 * 8);
    }
    for (int idx = tid; idx < LKEYS * 8; idx += 256) {
        const int row = idx >> 3, c16 = idx & 7;
        uint4 kv = make_uint4(0, 0, 0, 0), vv = make_uint4(0, 0, 0, 0);
        if (row < 384) {
            const int kp = base + row;
            if (kp >= 0 && kp < SS) {
                kv = *(const uint4*)(kb_ + (size_t)kp * DH + c16 * 8);
                vv = *(const uint4*)(vb_ + (size_t)kp * DH + c16 * 8);
            }
        } else if (row < 416) {
            kv = *(const uint4*)(kb_ + (size_t)(row - 384) * DH + c16 * 8);
            vv = *(const uint4*)(vb_ + (size_t)(row - 384) * DH + c16 * 8);
        }
        const uint32_t so = swz(row, c16);
        *(uint4*)(sm + 16384 + so) = kv;
        *(uint4*)(sm + 73728 + so) = vv;
    }
    for (int j = tid; j < LKEYS; j += 256) {
        float a;
        if (j < 384) {
            const int kp = base + j;
            a = (kp >= NGG && kp < SS) ? am[b * SS + kp] : NINF;
        } else if (j < 416) a = am[b * SS + (j - 384)];
        else a = NINF;
        ams[j] = a;
    }
    __syncthreads();

    const int wq = tid >> 5, lane = tid & 31;
    const int g = lane >> 2, quad = lane & 3;
    const int aRow = lane & 15, aChunk = lane >> 4;
    const int bRow = (lane & 7) + ((lane >> 4) << 3);
    const int bChunk = (lane >> 3) & 1;
    const int r0 = wq * 16 + g, r1 = r0 + 8;

    // Q fragments (resident)
    uint32_t qf[4][4];
#pragma unroll
    for (int u = 0; u < 4; u++) {
        const int row = wq * 16 + aRow;
        ldsm4(qf[u][0], qf[u][1], qf[u][2], qf[u][3], sQ + swz(row, u * 2 + aChunk));
    }

    float o[8][4];
#pragma unroll
    for (int t = 0; t < 8; t++)
#pragma unroll
        for (int i = 0; i < 4; i++) o[t][i] = 0.f;
    float m0 = -1e30f, m1 = -1e30f, l0 = 0.f, l1 = 0.f;

#pragma unroll 1
    for (int kb = 0; kb < 7; kb++) {
        float s[8][4];
#pragma unroll
        for (int t = 0; t < 8; t++)
#pragma unroll
            for (int i = 0; i < 4; i++) s[t][i] = 0.f;

#pragma unroll
        for (int u = 0; u < 4; u++) {
            uint32_t bf[8][2];
#pragma unroll
            for (int bp = 0; bp < 4; bp++) {
                const int nrow = kb * 64 + bp * 16 + bRow;
                ldsm4(bf[2*bp][0], bf[2*bp][1], bf[2*bp+1][0], bf[2*bp+1][1],
                      sK + swz(nrow, u * 2 + bChunk));
            }
#pragma unroll
            for (int t = 0; t < 8; t++) mma_f16(s[t], qf[u], bf[t]);
        }

        // mask + attention-mask add
#pragma unroll
        for (int t = 0; t < 8; t++) {
            const int n0 = kb * 64 + t * 8 + quad * 2, n1 = n0 + 1;
            const float a0 = ams[n0], a1 = ams[n1];
            s[t][0] = (n0 >= 384 || (n0 >= r0 && n0 <= r0 + 256)) ? s[t][0] + a0 : NINF;
            s[t][1] = (n1 >= 384 || (n1 >= r0 && n1 <= r0 + 256)) ? s[t][1] + a1 : NINF;
            s[t][2] = (n0 >= 384 || (n0 >= r1 && n0 <= r1 + 256)) ? s[t][2] + a0 : NINF;
            s[t][3] = (n1 >= 384 || (n1 >= r1 && n1 <= r1 + 256)) ? s[t][3] + a1 : NINF;
        }

        // row maxes
        float mx0 = NINF, mx1 = NINF;
#pragma unroll
        for (int t = 0; t < 8; t++) {
            mx0 = fmaxf(mx0, fmaxf(s[t][0], s[t][1]));
            mx1 = fmaxf(mx1, fmaxf(s[t][2], s[t][3]));
        }
        mx0 = fmaxf(mx0, __shfl_xor_sync(0xffffffffu, mx0, 1));
        mx0 = fmaxf(mx0, __shfl_xor_sync(0xffffffffu, mx0, 2));
        mx1 = fmaxf(mx1, __shfl_xor_sync(0xffffffffu, mx1, 1));
        mx1 = fmaxf(mx1, __shfl_xor_sync(0xffffffffu, mx1, 2));

        const float mn0 = fmaxf(m0, mx0), mn1 = fmaxf(m1, mx1);
        const float cr0 = __expf(m0 - mn0), cr1 = __expf(m1 - mn1);
        float sum0 = 0.f, sum1 = 0.f;
#pragma unroll
        for (int t = 0; t < 8; t++) {
            s[t][0] = __expf(s[t][0] - mn0); sum0 += s[t][0];
            s[t][1] = __expf(s[t][1] - mn0); sum0 += s[t][1];
            s[t][2] = __expf(s[t][2] - mn1); sum1 += s[t][2];
            s[t][3] = __expf(s[t][3] - mn1); sum1 += s[t][3];
        }
        sum0 += __shfl_xor_sync(0xffffffffu, sum0, 1);
        sum0 += __shfl_xor_sync(0xffffffffu, sum0, 2);
        sum1 += __shfl_xor_sync(0xffffffffu, sum1, 1);
        sum1 += __shfl_xor_sync(0xffffffffu, sum1, 2);
        l0 = l0 * cr0 + sum0;
        l1 = l1 * cr1 + sum1;
        m0 = mn0; m1 = mn1;
#pragma unroll
        for (int t = 0; t < 8; t++) {
            o[t][0] *= cr0; o[t][1] *= cr0;
            o[t][2] *= cr1; o[t][3] *= cr1;
        }

        // P fragments from S accumulators (no shuffles needed)
        uint32_t pa[4][4];
#pragma unroll
        for (int u = 0; u < 4; u++) {
            pa[u][0] = packh2(s[2*u][0],   s[2*u][1]);
            pa[u][1] = packh2(s[2*u][2],   s[2*u][3]);
            pa[u][2] = packh2(s[2*u+1][0], s[2*u+1][1]);
            pa[u][3] = packh2(s[2*u+1][2], s[2*u+1][3]);
        }

        // O += P @ V  (V via ldmatrix.trans)
#pragma unroll
        for (int u = 0; u < 4; u++) {
            uint32_t vb2[8][2];
#pragma unroll
            for (int dt = 0; dt < 4; dt++) {
                const int vrow = kb * 64 + u * 16 + aRow;
                ldsm4t(vb2[2*dt][0], vb2[2*dt][1], vb2[2*dt+1][0], vb2[2*dt+1][1],
                       sV + swz(vrow, dt * 2 + aChunk));
            }
#pragma unroll
            for (int t = 0; t < 8; t++) mma_f16(o[t], pa[u], vb2[t]);
        }
    }

    // epilogue
    const float i0 = 1.f / l0, i1 = 1.f / l1;
    const int s0 = c * WW + r0, s1 = s0 + 8;
#pragma unroll
    for (int t = 0; t < 8; t++) {
        const int d = t * 8 + quad * 2;
        if (s0 >= NGG)
            *(__half2*)&ctx16[((size_t)(b * SS + s0)) * DDIM + h * DH + d] =
                __floats2half2_rn(o[t][0] * i0, o[t][1] * i0);
        if (s1 >= NGG)
            *(__half2*)&ctx16[((size_t)(b * SS + s1)) * DDIM + h * DH + d] =
                __floats2half2_rn(o[t][2] * i1, o[t][3] * i1);
    }
}

// ---------------- global-row attention, phase 1 -----------------------------
#define GPA_SMEM ((GKEYS*64*2 + 32*65 + GKEYS) * sizeof(float))

__global__ __launch_bounds__(256)
void global_attn_part(const float* __restrict__ q, const float* __restrict__ k,
                      const float* __restrict__ v, const float* __restrict__ am,
                      float* __restrict__ gsc)
{
    extern __shared__ float smf[];
    float* ks  = smf;
    float* vs  = ks + GKEYS * 64;
    float* qs  = vs + GKEYS * 64;
    float* ams = qs + 32 * 65;

    const int sp = blockIdx.x, bh = blockIdx.y;
    const int b = bh / NHH;
    const int tid = threadIdx.x;
    const int base = sp * GKEYS;
    const float* kb = k + (size_t)bh * SS * DH;
    const float* vb = v + (size_t)bh * SS * DH;

    for (int i = tid; i < GKEYS * 64; i += 256) {
        ks[i] = kb[(size_t)base * 64 + i];
        vs[i] = vb[(size_t)base * 64 + i];
    }
    for (int i = tid; i < 32 * 64; i += 256)
        qs[(i >> 6) * 65 + (i & 63)] = q[(size_t)bh * SS * DH + i];
    if (tid < GKEYS) ams[tid] = am[b * SS + base + tid];
    __syncthreads();

    const int row = tid & 31, seg = tid >> 5;
    float qr[64];
#pragma unroll
    for (int d = 0; d < 64; d++) qr[d] = qs[row * 65 + d];

    float mval = -1e30f, l = 0.f;
    float acc[64];
#pragma unroll
    for (int d = 0; d < 64; d++) acc[d] = 0.f;

    const int jj0 = seg * 32, jj1 = jj0 + 32;
    for (int j = jj0; j < jj1; j++) {
        const float4* kr = (const float4*)&ks[j * 64];
        float s0 = 0.f, s1 = 0.f, s2 = 0.f, s3 = 0.f;
#pragma unroll
        for (int d4 = 0; d4 < 16; d4++) {
            const float4 kv = kr[d4];
            s0 += qr[d4*4+0] * kv.x;
            s1 += qr[d4*4+1] * kv.y;
            s2 += qr[d4*4+2] * kv.z;
            s3 += qr[d4*4+3] * kv.w;
        }
        const float sc = (s0 + s1) + (s2 + s3) + ams[j];
        const float mn = fmaxf(mval, sc);
        const float corr = __expf(mval - mn);
        const float p = __expf(sc - mn);
        l = l * corr + p;
        const float4* vr = (const float4*)&vs[j * 64];
#pragma unroll
        for (int d4 = 0; d4 < 16; d4++) {
            const float4 vv = vr[d4];
            acc[d4*4+0] = acc[d4*4+0] * corr + p * vv.x;
            acc[d4*4+1] = acc[d4*4+1] * corr + p * vv.y;
            acc[d4*4+2] = acc[d4*4+2] * corr + p * vv.z;
            acc[d4*4+3] = acc[d4*4+3] * corr + p * vv.w;
        }
        mval = mn;
    }

    __syncthreads();
    float* scr = ks;
    float* sp_ = scr + (row * 8 + seg) * 66;
    sp_[0] = mval; sp_[1] = l;
#pragma unroll
    for (int d = 0; d < 64; d++) sp_[2 + d] = acc[d];
    __syncthreads();

    if (seg == 0) {
        float mstar = -1e30f;
#pragma unroll
        for (int t = 0; t < 8; t++) mstar = fmaxf(mstar, scr[(row * 8 + t) * 66]);
        float lstar = 0.f;
        float out[64];
#pragma unroll
        for (int d = 0; d < 64; d++) out[d] = 0.f;
#pragma unroll
        for (int t = 0; t < 8; t++) {
            const float* pp = scr + (row * 8 + t) * 66;
            const float w = __expf(pp[0] - mstar);
            lstar += pp[1] * w;
#pragma unroll
            for (int d = 0; d < 64; d++) out[d] += pp[2 + d] * w;
        }
        float* gp = gsc + (((size_t)bh * GSPLIT + sp) * NGG + row) * 66;
        gp[0] = mstar; gp[1] = lstar;
#pragma unroll
        for (int d = 0; d < 64; d++) gp[2 + d] = out[d];
    }
}

// ---------------- global-row attention, phase 2 -----------------------------
__global__ __launch_bounds__(256)
void global_attn_merge(const float* __restrict__ gsc, __half* __restrict__ ctx16)
{
    const int bh = blockIdx.x;
    const int b = bh / NHH, h = bh % NHH;
    const int tid = threadIdx.x;
    const int row = tid >> 3, dc = (tid & 7) * 8;

    const float* rp = gsc + ((size_t)bh * GSPLIT * NGG + row) * 66;
    float mstar = -1e30f;
#pragma unroll
    for (int s = 0; s < GSPLIT; s++)
        mstar = fmaxf(mstar, rp[(size_t)s * NGG * 66]);
    float lstar = 0.f;
    float out[8];
#pragma unroll
    for (int d = 0; d < 8; d++) out[d] = 0.f;
#pragma unroll
    for (int s = 0; s < GSPLIT; s++) {
        const float* pp = rp + (size_t)s * NGG * 66;
        const float w = __expf(pp[0] - mstar);
        lstar += pp[1] * w;
#pragma unroll
        for (int d = 0; d < 8; d++) out[d] += pp[2 + dc + d] * w;
    }
    const float inv = 1.f / lstar;
    const size_t ob = ((size_t)(b * SS + row)) * DDIM + h * DH + dc;
#pragma unroll
    for (int d = 0; d < 8; d += 2)
        *(__half2*)&ctx16[ob + d] = __floats2half2_rn(out[d] * inv, out[d + 1] * inv);
}

// ---------------- layernorm with fused combine ------------------------------
__global__ __launch_bounds__(256)
void ln_combine(const float* __restrict__ P0, const float* __restrict__ P1,
                const float* __restrict__ Res, const float* __restrict__ bias,
                const float* __restrict__ gw, const float* __restrict__ bw,
                float* __restrict__ Y, __half* __restrict__ Yh)
{
    __shared__ float xs[DDIM];
    __shared__ float red[256];
    const int row = blockIdx.x, tid = threadIdx.x;
    const size_t bo = (size_t)row * DDIM;

    float sum = 0.f;
    for (int i = tid; i < DDIM; i += 256) {
        const float t = P0[bo + i] + P1[bo + i] + Res[bo + i] + bias[i];
        xs[i] = t; sum += t;
    }
    red[tid] = sum;
    __syncthreads();
    for (int st = 128; st > 0; st >>= 1) {
        if (tid < st) red[tid] += red[tid + st];
        __syncthreads();
    }
    const float mu = red[0] * (1.f / DDIM);
    __syncthreads();

    float vsum = 0.f;
    for (int i = tid; i < DDIM; i += 256) { const float d = xs[i] - mu; vsum += d * d; }
    red[tid] = vsum;
    __syncthreads();
    for (int st = 128; st > 0; st >>= 1) {
        if (tid < st) red[tid] += red[tid + st];
        __syncthreads();
    }
    const float rstd = rsqrtf(red[0] * (1.f / DDIM) + 1e-12f);
    for (int i = tid; i < DDIM; i += 256) {
        const float val = (xs[i] - mu) * rstd * gw[i] + bw[i];
        Y[bo + i] = val;
        if (Yh) Yh[bo + i] = __float2half(val);
    }
}

// ---------------- launch ----------------------------------------------------
extern "C" void kernel_launch(void* const* d_in, const int* in_sizes, int n_in,
                              void* d_out, int out_size)
{
    const float* h    = (const float*)d_in[0];
    const float* am   = (const float*)d_in[1];
    const float* Wq   = (const float*)d_in[2];
    const float* bq   = (const float*)d_in[3];
    const float* Wk   = (const float*)d_in[4];
    const float* bk   = (const float*)d_in[5];
    const float* Wv   = (const float*)d_in[6];
    const float* bv   = (const float*)d_in[7];
    const float* Wo   = (const float*)d_in[8];
    const float* bo   = (const float*)d_in[9];
    const float* ln1g = (const float*)d_in[10];
    const float* ln1b = (const float*)d_in[11];
    const float* Wi   = (const float*)d_in[12];
    const float* bi   = (const float*)d_in[13];
    const float* Wo2  = (const float*)d_in[14];
    const float* bo2  = (const float*)d_in[15];
    const float* ln2g = (const float*)d_in[16];
    const float* ln2b = (const float*)d_in[17];

    float *q, *k, *v, *x1, *x2, *attn, *gsc;
    __half *h16, *ctx16, *at16, *in16, *q16, *k16, *v16;
    __half *wqkvt, *wot, *wit, *wo2t;
    cudaGetSymbolAddress((void**)&q,    g_q);
    cudaGetSymbolAddress((void**)&k,    g_k);
    cudaGetSymbolAddress((void**)&v,    g_v);
    cudaGetSymbolAddress((void**)&x1,   g_x1);
    cudaGetSymbolAddress((void**)&x2,   g_x2);
    cudaGetSymbolAddress((void**)&attn, g_attn);
    cudaGetSymbolAddress((void**)&gsc,  g_gsc);
    cudaGetSymbolAddress((void**)&h16,  g_h16);
    cudaGetSymbolAddress((void**)&ctx16,g_ctx16);
    cudaGetSymbolAddress((void**)&at16, g_at16);
    cudaGetSymbolAddress((void**)&in16, g_in16);
    cudaGetSymbolAddress((void**)&q16,  g_q16);
    cudaGetSymbolAddress((void**)&k16,  g_k16);
    cudaGetSymbolAddress((void**)&v16,  g_v16);
    cudaGetSymbolAddress((void**)&wqkvt,g_wqkvt);
    cudaGetSymbolAddress((void**)&wot,  g_wot);
    cudaGetSymbolAddress((void**)&wit,  g_wit);
    cudaGetSymbolAddress((void**)&wo2t, g_wo2t);

    cudaFuncSetAttribute(local_attn_mma, cudaFuncAttributeMaxDynamicSharedMemorySize, (int)LA_SMEM);
    cudaFuncSetAttribute(global_attn_part, cudaFuncAttributeMaxDynamicSharedMemorySize, (int)GPA_SMEM);
    cudaFuncSetAttribute(gemm_f16<EP_QKV>,  cudaFuncAttributeMaxDynamicSharedMemorySize, SMEM16);
    cudaFuncSetAttribute(gemm_f16<EP_GELU>, cudaFuncAttributeMaxDynamicSharedMemorySize, SMEM16);
    cudaFuncSetAttribute(gemm_f16<EP_PART>, cudaFuncAttributeMaxDynamicSharedMemorySize, SMEM16);

    // --- prepare fp16 operands ---
    convert_f16<<<(MM * DDIM / 4 + 255) / 256, 256>>>(h, h16, MM * DDIM / 4);
    transpose_f16<<<dim3(DDIM / 32, DDIM / 32), 256>>>(Wq, wqkvt,                DDIM, DDIM);
    transpose_f16<<<dim3(DDIM / 32, DDIM / 32), 256>>>(Wk, wqkvt + DDIM * DDIM,  DDIM, DDIM);
    transpose_f16<<<dim3(DDIM / 32, DDIM / 32), 256>>>(Wv, wqkvt + 2*DDIM*DDIM,  DDIM, DDIM);
    transpose_f16<<<dim3(DDIM / 32, DDIM / 32), 256>>>(Wo, wot, DDIM, DDIM);
    transpose_f16<<<dim3(FF / 32,   DDIM / 32), 256>>>(Wi,  wit,  DDIM, FF);
    transpose_f16<<<dim3(DDIM / 32, FF / 32),   256>>>(Wo2, wo2t, FF, DDIM);

    // --- merged QKV projection (fp32 + fp16 outputs) ---
    gemm_f16<EP_QKV><<<dim3(3 * DDIM / 128, MM / 128), 256, SMEM16>>>(
        h16, wqkvt, bq, bk, bv, q, k, v, nullptr, q16, k16, v16, MM, 3 * DDIM, DDIM, DDIM);

    // --- attention ---
    local_attn_mma<<<dim3(CC, BB * NHH), 256, LA_SMEM>>>(q16, k16, v16, am, ctx16);
    global_attn_part<<<dim3(GSPLIT, BB * NHH), 256, GPA_SMEM>>>(q, k, v, am, gsc);
    global_attn_merge<<<BB * NHH, 256>>>(gsc, ctx16);

    // --- output projection split-K x2, LN1 fused combine ---
    gemm_f16<EP_PART><<<dim3(DDIM / 128, MM / 128, 2), 256, SMEM16>>>(
        ctx16, wot, nullptr, nullptr, nullptr, x2, k, nullptr, nullptr,
        nullptr, nullptr, nullptr, MM, DDIM, DDIM / 2, DDIM);
    ln_combine<<<MM, 256>>>(x2, k, h, bo, ln1g, ln1b, attn, at16);

    // --- FFN ---
    gemm_f16<EP_GELU><<<dim3(FF / 128, MM / 128), 256, SMEM16>>>(
        at16, wit, bi, nullptr, nullptr, nullptr, nullptr, nullptr, in16,
        nullptr, nullptr, nullptr, MM, FF, DDIM, DDIM);
    gemm_f16<EP_PART><<<dim3(DDIM / 128, MM / 128, 2), 256, SMEM16>>>(
        in16, wo2t, nullptr, nullptr, nullptr, x1, q, nullptr, nullptr,
        nullptr, nullptr, nullptr, MM, DDIM, FF / 2, FF);
    ln_combine<<<MM, 256>>>(x1, q, attn, bo2, ln2g, ln2b, (float*)d_out, nullptr);
}